// round 15
// baseline (speedup 1.0000x reference)
#include <cuda_runtime.h>
#include <cuda_bf16.h>
#include <math.h>
#include <cstdint>

#define NE  256
#define P_TOTAL 32640
#define PPB 16
#define MTOK 32                        /* 2*PPB tokens per CTA */
#define NBLOCKS (P_TOTAL/PPB)          /* 2040 */
#define NTHREADS 256
#define RS  264                        /* padded row stride, bf16 elems */
#define RSB (RS*2)                     /* 528 bytes */
#define PL  (MTOK*RS)                  /* one activation plane, halves */
#define PLB (PL*2)                     /* plane bytes (16896) */
#define WBUF1 (32*RS*2)                /* one chunk buf: 16 hi + 16 lo rows = 16896 B */
#define SMEM_BYTES (4*PLB + 2*WBUF1)   /* 67584 + 33792 = 101376 -> 2 CTAs/SM */

// ---------------- device globals (no allocations) --------------------------
// split-bf16 weights: slots 1=Wq_1, 2=Wk_1, 3=Wv_1, 4=WoW1_1, 5=W2_1
__device__ __nv_bfloat16 g_Ws_hi[6*65536];
__device__ __nv_bfloat16 g_Ws_lo[6*65536];
__device__ __align__(16) float g_h0[65536];
__device__ __align__(16) float g_q0[65536], g_k0[65536], g_v0[65536];
__device__ __align__(16) float g_G[4*65536];
__device__ __align__(16) float g_Z[65536*4];
__device__ __align__(16) float g_WoW1[2*65536];
__device__ __align__(16) float g_boW1[2*256];
__device__ __align__(16) float g_Ph0[65536];
__device__ __align__(16) float g_PZ[65536*4];
__device__ __align__(16) float g_c1[256], g_c2[256], g_c3[256];
__device__ float2 g_A[NE*NE];
__device__ double g_acc[2];
__device__ double g_lu_logabs, g_lu_arg;
__device__ int    g_lu_par;

// ---------------- helpers ---------------------------------------------------
__device__ __forceinline__ uint32_t smem_u32(const void* p) {
    return (uint32_t)__cvta_generic_to_shared(p);
}
__device__ __forceinline__ void sst(__nv_bfloat16* h, __nv_bfloat16* l, float x) {
    __nv_bfloat16 hi = __float2bfloat16_rn(x);
    *h = hi;
    *l = __float2bfloat16_rn(x - __bfloat162float(hi));
}
__device__ __forceinline__ float rec(const __nv_bfloat16* h, const __nv_bfloat16* l, int idx) {
    return __bfloat162float(h[idx]) + __bfloat162float(l[idx]);
}

// ---------------- precompute kernels (unchanged, proven) --------------------
__global__ void wow1_kernel(const float* __restrict__ Wo, const float* __restrict__ W1,
                            const float* __restrict__ bo)
{
    int b = blockIdx.x, col = threadIdx.x;
    int l = b / 257, r = b % 257;
    const float* W1l = W1 + l*65536;
    float acc = 0.f;
    if (r < 256) {
        const float* Wol = Wo + l*65536 + r*256;
        for (int d = 0; d < 256; d++) acc = fmaf(Wol[d], W1l[d*256 + col], acc);
        g_WoW1[l*65536 + r*256 + col] = acc;
    } else {
        const float* bol = bo + l*256;
        for (int d = 0; d < 256; d++) acc = fmaf(bol[d], W1l[d*256 + col], acc);
        g_boW1[l*256 + col] = acc;
    }
}

__global__ void prep_kernel(const float* __restrict__ electrons, const float* __restrict__ W_in,
                            const float* __restrict__ Wq, const float* __restrict__ bq,
                            const float* __restrict__ Wk, const float* __restrict__ bk,
                            const float* __restrict__ Wv, const float* __restrict__ bv)
{
    __shared__ float hrow[256];
    int e = blockIdx.x, col = threadIdx.x;
    float th = electrons[2*e], ph = electrons[2*e+1];
    float st, ct, sp, cp;
    sincosf(th, &st, &ct);
    sincosf(ph, &sp, &cp);
    float f0 = ct, f1 = st*cp, f2 = st*sp;
    float h = f0*__ldg(W_in + col) + f1*__ldg(W_in + 256 + col) + f2*__ldg(W_in + 512 + col);
    g_h0[e*256 + col] = h;
    hrow[col] = h;
    __syncthreads();
    float q = __ldg(bq + col), k = __ldg(bk + col), v = __ldg(bv + col);
    for (int d = 0; d < 256; d++) {
        float hv = hrow[d];
        q = fmaf(hv, __ldg(Wq + d*256 + col), q);
        k = fmaf(hv, __ldg(Wk + d*256 + col), k);
        v = fmaf(hv, __ldg(Wv + d*256 + col), v);
    }
    g_q0[e*256 + col] = q;
    g_k0[e*256 + col] = k;
    g_v0[e*256 + col] = v;
}

__global__ void gram_z_kernel()
{
    __shared__ float qrow[256], vrow[256];
    int i = blockIdx.x, t = threadIdx.x;
    qrow[t] = g_q0[i*256 + t];
    vrow[t] = g_v0[i*256 + t];
    __syncthreads();
    #pragma unroll
    for (int h = 0; h < 4; h++) {
        float acc = 0.f;
        const float* krow = g_k0 + t*256 + h*64;
        #pragma unroll 8
        for (int d = 0; d < 64; d++) acc = fmaf(qrow[h*64 + d], __ldg(krow + d), acc);
        g_G[h*65536 + i*256 + t] = acc * 0.125f;
    }
    #pragma unroll
    for (int h = 0; h < 4; h++) {
        float acc = 0.f;
        #pragma unroll 8
        for (int d = 0; d < 64; d++)
            acc = fmaf(vrow[h*64 + d], __ldg(g_WoW1 + (h*64 + d)*256 + t), acc);
        g_Z[i*1024 + h*256 + t] = acc;
    }
}

__global__ void pbasis_kernel(const float* __restrict__ W2, const float* __restrict__ ln1_s,
                              const float* __restrict__ ln1_b)
{
    __shared__ float src[256];
    int b = blockIdx.x, col = threadIdx.x;
    if (b < 256) {
        src[col] = g_h0[b*256 + col] * __ldg(ln1_s + col);
        __syncthreads();
        float acc = 0.f;
        for (int d = 0; d < 256; d++) acc = fmaf(src[d], __ldg(W2 + d*256 + col), acc);
        g_Ph0[b*256 + col] = acc;
    } else if (b < 1280) {
        int idx = b - 256;
        src[col] = g_Z[idx*256 + col] * __ldg(ln1_s + col);
        __syncthreads();
        float acc = 0.f;
        for (int d = 0; d < 256; d++) acc = fmaf(src[d], __ldg(W2 + d*256 + col), acc);
        g_PZ[idx*256 + col] = acc;
    } else {
        src[col] = g_boW1[col] * __ldg(ln1_s + col);
        __syncthreads();
        float a1 = 0.f, a2 = 0.f, a3 = 0.f;
        for (int d = 0; d < 256; d++) {
            float w = __ldg(W2 + d*256 + col);
            a1 = fmaf(src[d], w, a1);
            a2 = fmaf(__ldg(ln1_s + d), w, a2);
            a3 = fmaf(__ldg(ln1_b + d), w, a3);
        }
        g_c1[col] = a1; g_c2[col] = a2; g_c3[col] = a3;
    }
}

__global__ void convert_host(const float* __restrict__ Wq, const float* __restrict__ Wk,
                             const float* __restrict__ Wv, const float* __restrict__ W2)
{
    int idx = blockIdx.x * 256 + threadIdx.x;
    int m = idx >> 16, off = idx & 65535;
    const float* src; int slot;
    switch (m) {
        case 0: src = Wq + 65536;  slot = 1; break;
        case 1: src = Wk + 65536;  slot = 2; break;
        case 2: src = Wv + 65536;  slot = 3; break;
        default: src = W2 + 65536; slot = 5; break;
    }
    float v = src[off];
    __nv_bfloat16 hi = __float2bfloat16_rn(v);
    g_Ws_hi[slot*65536 + off] = hi;
    g_Ws_lo[slot*65536 + off] = __float2bfloat16_rn(v - __bfloat162float(hi));
}

__global__ void convert_wow1()
{
    int idx = blockIdx.x * 256 + threadIdx.x;
    float v = g_WoW1[65536 + idx];
    __nv_bfloat16 hi = __float2bfloat16_rn(v);
    g_Ws_hi[4*65536 + idx] = hi;
    g_Ws_lo[4*65536 + idx] = __float2bfloat16_rn(v - __bfloat162float(hi));
}

// ---------------- split-bf16 GEMM: 16-row chunks, double-buffered -----------
// chunk buf layout: rows 0..15 = hi k-rows, rows 16..31 = lo k-rows
__device__ __forceinline__ void cp_load16(const __nv_bfloat16* __restrict__ gWhi,
                                          const __nv_bfloat16* __restrict__ gWlo,
                                          int chunk, uint32_t buf, int tid)
{
    #pragma unroll
    for (int i = 0; i < 4; i++) {
        int g = tid + i*NTHREADS;             // 1024 granules of 16B
        int plane = g >> 9;                   // 0=hi, 1=lo
        int row = (g >> 5) & 15, c16 = g & 31;
        uint32_t s = buf + (plane*16 + row)*RSB + c16*16;
        const __nv_bfloat16* base = plane ? gWlo : gWhi;
        const void* gp = base + (chunk*16 + row)*256 + c16*8;
        asm volatile("cp.async.cg.shared.global [%0],[%1],16;\n" :: "r"(s), "l"(gp));
    }
    asm volatile("cp.async.commit_group;\n");
}

// prefetch chunk 0 into buffer 0 (call as early as possible before mma_gemm)
__device__ __forceinline__ void gemm_prefetch(const __nv_bfloat16* __restrict__ gWhi,
                                              const __nv_bfloat16* __restrict__ gWlo,
                                              uint32_t sW, int tid)
{
    cp_load16(gWhi, gWlo, 0, sW, tid);
}

// assumes chunk 0 already issued into buffer 0 (via gemm_prefetch)
__device__ __forceinline__ void mma_gemm(const __nv_bfloat16* __restrict__ gWhi,
                                         const __nv_bfloat16* __restrict__ gWlo,
                                         uint32_t sA, uint32_t sW,
                                         float C[2][4][4], int tid)
{
    int lane = tid & 31, warp = tid >> 5;
    #pragma unroll
    for (int a = 0; a < 2; a++)
        #pragma unroll
        for (int b = 0; b < 4; b++)
            #pragma unroll
            for (int d = 0; d < 4; d++) C[a][b][d] = 0.f;

    #pragma unroll 1
    for (int c = 0; c < 16; c++) {
        if (c < 15) {
            cp_load16(gWhi, gWlo, c+1, sW + ((c+1)&1)*WBUF1, tid);
            asm volatile("cp.async.wait_group 1;\n");
        } else {
            asm volatile("cp.async.wait_group 0;\n");
        }
        __syncthreads();
        uint32_t wb = sW + (c&1)*WBUF1;
        int k0 = c*16;
        uint32_t ahi[2][4], alo[2][4], bhi[2][4], blo[2][4];
        #pragma unroll
        for (int mi = 0; mi < 2; mi++) {
            uint32_t addr = sA + (mi*16 + (lane & 15))*RSB + (k0 + ((lane >> 4) << 3))*2;
            asm volatile("ldmatrix.sync.aligned.m8n8.x4.shared.b16 {%0,%1,%2,%3},[%4];\n"
                : "=r"(ahi[mi][0]), "=r"(ahi[mi][1]), "=r"(ahi[mi][2]), "=r"(ahi[mi][3]) : "r"(addr));
            asm volatile("ldmatrix.sync.aligned.m8n8.x4.shared.b16 {%0,%1,%2,%3},[%4];\n"
                : "=r"(alo[mi][0]), "=r"(alo[mi][1]), "=r"(alo[mi][2]), "=r"(alo[mi][3]) : "r"(addr + PLB));
        }
        #pragma unroll
        for (int nh = 0; nh < 2; nh++) {
            uint32_t addr = wb + (lane & 15)*RSB
                          + (warp*32 + nh*16 + ((lane >> 4) << 3))*2;
            asm volatile("ldmatrix.sync.aligned.m8n8.x4.trans.shared.b16 {%0,%1,%2,%3},[%4];\n"
                : "=r"(bhi[nh][0]), "=r"(bhi[nh][1]), "=r"(bhi[nh][2]), "=r"(bhi[nh][3]) : "r"(addr));
            asm volatile("ldmatrix.sync.aligned.m8n8.x4.trans.shared.b16 {%0,%1,%2,%3},[%4];\n"
                : "=r"(blo[nh][0]), "=r"(blo[nh][1]), "=r"(blo[nh][2]), "=r"(blo[nh][3]) : "r"(addr + 16*RSB));
        }
        #pragma unroll
        for (int mi = 0; mi < 2; mi++)
            #pragma unroll
            for (int ni = 0; ni < 4; ni++) {
                uint32_t bh0 = bhi[ni>>1][(ni&1)*2], bh1 = bhi[ni>>1][(ni&1)*2 + 1];
                uint32_t bl0 = blo[ni>>1][(ni&1)*2], bl1 = blo[ni>>1][(ni&1)*2 + 1];
                asm volatile("mma.sync.aligned.m16n8k16.row.col.f32.bf16.bf16.f32 "
                    "{%0,%1,%2,%3},{%4,%5,%6,%7},{%8,%9},{%0,%1,%2,%3};\n"
                    : "+f"(C[mi][ni][0]), "+f"(C[mi][ni][1]),
                      "+f"(C[mi][ni][2]), "+f"(C[mi][ni][3])
                    : "r"(ahi[mi][0]), "r"(ahi[mi][1]), "r"(ahi[mi][2]), "r"(ahi[mi][3]),
                      "r"(bh0), "r"(bh1));
                asm volatile("mma.sync.aligned.m16n8k16.row.col.f32.bf16.bf16.f32 "
                    "{%0,%1,%2,%3},{%4,%5,%6,%7},{%8,%9},{%0,%1,%2,%3};\n"
                    : "+f"(C[mi][ni][0]), "+f"(C[mi][ni][1]),
                      "+f"(C[mi][ni][2]), "+f"(C[mi][ni][3])
                    : "r"(alo[mi][0]), "r"(alo[mi][1]), "r"(alo[mi][2]), "r"(alo[mi][3]),
                      "r"(bh0), "r"(bh1));
                asm volatile("mma.sync.aligned.m16n8k16.row.col.f32.bf16.bf16.f32 "
                    "{%0,%1,%2,%3},{%4,%5,%6,%7},{%8,%9},{%0,%1,%2,%3};\n"
                    : "+f"(C[mi][ni][0]), "+f"(C[mi][ni][1]),
                      "+f"(C[mi][ni][2]), "+f"(C[mi][ni][3])
                    : "r"(ahi[mi][0]), "r"(ahi[mi][1]), "r"(ahi[mi][2]), "r"(ahi[mi][3]),
                      "r"(bl0), "r"(bl1));
            }
        __syncthreads();
    }
}

// add per-column bias into a register fragment
__device__ __forceinline__ void frag_add_bias(float C[2][4][4], const float* __restrict__ b,
                                              int lane, int warp)
{
    #pragma unroll
    for (int ni = 0; ni < 4; ni++) {
        int col = warp*32 + ni*8 + (lane & 3)*2;
        float v0 = __ldg(b + col), v1 = __ldg(b + col + 1);
        #pragma unroll
        for (int mi = 0; mi < 2; mi++)
            #pragma unroll
            for (int hf = 0; hf < 2; hf++) {
                C[mi][ni][hf*2]   += v0;
                C[mi][ni][hf*2+1] += v1;
            }
    }
}

// layernorm in place: 8 warps x 4 rows
__device__ __forceinline__ void lnorm(__nv_bfloat16* Hh, __nv_bfloat16* Hl,
                                      const float* __restrict__ sc,
                                      const float* __restrict__ bi, int tid)
{
    int lane = tid & 31, warp = tid >> 5;
    #pragma unroll 1
    for (int rr = 0; rr < 4; rr++) {
        int row = warp*4 + rr;
        float xs[8];
        float s1 = 0.f, s2 = 0.f;
        #pragma unroll
        for (int i = 0; i < 8; i++) {
            int col = lane*8 + i;
            float f = rec(Hh, Hl, row*RS + col);
            xs[i] = f;
            s1 += f; s2 += f*f;
        }
        #pragma unroll
        for (int off = 16; off; off >>= 1) {
            s1 += __shfl_xor_sync(0xffffffffu, s1, off);
            s2 += __shfl_xor_sync(0xffffffffu, s2, off);
        }
        float m   = s1 * (1.f/256.f);
        float var = s2 * (1.f/256.f) - m*m;
        float inv = rsqrtf(var + 1e-5f);
        #pragma unroll
        for (int i = 0; i < 8; i++) {
            int col = lane*8 + i;
            float y = (xs[i] - m)*inv*__ldg(sc+col) + __ldg(bi+col);
            sst(Hh + row*RS + col, Hl + row*RS + col, y);
        }
    }
}

// ---------------- pair transformer ------------------------------------------
__global__ void __launch_bounds__(NTHREADS, 2) pair_kernel(
    const float* __restrict__ electrons,
    const float* __restrict__ bq, const float* __restrict__ bk,
    const float* __restrict__ bv,
    const float* __restrict__ ln1_s, const float* __restrict__ ln1_b,
    const float* __restrict__ b2,
    const float* __restrict__ ln2_s, const float* __restrict__ ln2_b,
    const float* __restrict__ Worb_r, const float* __restrict__ Worb_i)
{
    extern __shared__ __nv_bfloat16 smem[];
    __nv_bfloat16* Hh = smem;
    __nv_bfloat16* Hl = Hh + PL;
    __nv_bfloat16* Oh = Hl + PL;
    __nv_bfloat16* Ol = Oh + PL;
    uint32_t sHb = smem_u32(Hh), sOb = smem_u32(Oh);
    uint32_t sWb = smem_u32(Ol + PL);

    __shared__ float s_tp[PPB][2][2];
    __shared__ int   s_ij[PPB][2];
    __shared__ float s_part[MTOK][4][2];
    __shared__ float s_attn[PPB][4][2][2];
    __shared__ float s_orb[PPB][8];

    int tid = threadIdx.x;
    int lane = tid & 31, warp = tid >> 5;

    // prefetch Wq chunk 0 as early as possible
    gemm_prefetch(g_Ws_hi + 1*65536, g_Ws_lo + 1*65536, sWb, tid);

    // ---- pair index decode ----
    if (tid < PPB) {
        long long p = (long long)blockIdx.x * PPB + tid;
        double pd = (double)p;
        int i = (int)floor((2.0*NE - 1.0 - sqrt((2.0*NE-1.0)*(2.0*NE-1.0) - 8.0*pd)) * 0.5);
        if (i < 0) i = 0;
        if (i > NE-2) i = NE-2;
        while (i > 0 && (long long)i*(2*NE-1-i)/2 > p) i--;
        while ((long long)(i+1)*(2*NE-1-(i+1))/2 <= p) i++;
        long long base = (long long)i*(2*NE-1-i)/2;
        int j = (int)(p - base) + i + 1;
        s_ij[tid][0] = i; s_ij[tid][1] = j;
    }
    __syncthreads();
    if (tid < PPB*2) {
        int p = tid >> 1, s = tid & 1;
        int e = s_ij[p][s];
        s_tp[p][s][0] = electrons[2*e];
        s_tp[p][s][1] = electrons[2*e+1];
    }
    {
        float* sp = &s_part[0][0][0];
        if (tid < MTOK*4*2) sp[tid] = 0.f;
    }
    __syncthreads();

    // ---- layer 0 fully analytic -> H planes (8 warps x 2 pairs) ----
    #pragma unroll 1
    for (int pq = 0; pq < 2; pq++) {
        int pr = warp*2 + pq;
        int ei = s_ij[pr][0], ej = s_ij[pr][1];
        float a0s[2][4], a1s[2][4];
        #pragma unroll
        for (int s = 0; s < 2; s++) {
            int self = s ? ej : ei;
            #pragma unroll
            for (int h = 0; h < 4; h++) {
                float l0 = __ldg(g_G + h*65536 + self*256 + ei);
                float l1 = __ldg(g_G + h*65536 + self*256 + ej);
                float mx = fmaxf(l0, l1);
                float e0 = expf(l0 - mx), e1 = expf(l1 - mx);
                float inv = 1.f / (e0 + e1);
                a0s[s][h] = e0 * inv;
                a1s[s][h] = e1 * inv;
            }
        }
        int col0 = lane*8;
        float acc0[8], acc1[8], ap0[8], ap1[8];
        {
            float4 bw0 = __ldg((const float4*)(g_boW1 + col0));
            float4 bw1 = __ldg((const float4*)(g_boW1 + col0 + 4));
            float4 hi0 = __ldg((const float4*)(g_h0 + ei*256 + col0));
            float4 hi1 = __ldg((const float4*)(g_h0 + ei*256 + col0 + 4));
            float4 hj0 = __ldg((const float4*)(g_h0 + ej*256 + col0));
            float4 hj1 = __ldg((const float4*)(g_h0 + ej*256 + col0 + 4));
            acc0[0]=hi0.x+bw0.x; acc0[1]=hi0.y+bw0.y; acc0[2]=hi0.z+bw0.z; acc0[3]=hi0.w+bw0.w;
            acc0[4]=hi1.x+bw1.x; acc0[5]=hi1.y+bw1.y; acc0[6]=hi1.z+bw1.z; acc0[7]=hi1.w+bw1.w;
            acc1[0]=hj0.x+bw0.x; acc1[1]=hj0.y+bw0.y; acc1[2]=hj0.z+bw0.z; acc1[3]=hj0.w+bw0.w;
            acc1[4]=hj1.x+bw1.x; acc1[5]=hj1.y+bw1.y; acc1[6]=hj1.z+bw1.z; acc1[7]=hj1.w+bw1.w;
            float4 c10 = __ldg((const float4*)(g_c1 + col0));
            float4 c11 = __ldg((const float4*)(g_c1 + col0 + 4));
            float4 pi0 = __ldg((const float4*)(g_Ph0 + ei*256 + col0));
            float4 pi1 = __ldg((const float4*)(g_Ph0 + ei*256 + col0 + 4));
            float4 pj0 = __ldg((const float4*)(g_Ph0 + ej*256 + col0));
            float4 pj1 = __ldg((const float4*)(g_Ph0 + ej*256 + col0 + 4));
            ap0[0]=pi0.x+c10.x; ap0[1]=pi0.y+c10.y; ap0[2]=pi0.z+c10.z; ap0[3]=pi0.w+c10.w;
            ap0[4]=pi1.x+c11.x; ap0[5]=pi1.y+c11.y; ap0[6]=pi1.z+c11.z; ap0[7]=pi1.w+c11.w;
            ap1[0]=pj0.x+c10.x; ap1[1]=pj0.y+c10.y; ap1[2]=pj0.z+c10.z; ap1[3]=pj0.w+c10.w;
            ap1[4]=pj1.x+c11.x; ap1[5]=pj1.y+c11.y; ap1[6]=pj1.z+c11.z; ap1[7]=pj1.w+c11.w;
        }
        #pragma unroll
        for (int h = 0; h < 4; h++) {
            float4 zi0 = __ldg((const float4*)(g_Z + ei*1024 + h*256 + col0));
            float4 zi1 = __ldg((const float4*)(g_Z + ei*1024 + h*256 + col0 + 4));
            float4 zj0 = __ldg((const float4*)(g_Z + ej*1024 + h*256 + col0));
            float4 zj1 = __ldg((const float4*)(g_Z + ej*1024 + h*256 + col0 + 4));
            float4 qi0 = __ldg((const float4*)(g_PZ + ei*1024 + h*256 + col0));
            float4 qi1 = __ldg((const float4*)(g_PZ + ei*1024 + h*256 + col0 + 4));
            float4 qj0 = __ldg((const float4*)(g_PZ + ej*1024 + h*256 + col0));
            float4 qj1 = __ldg((const float4*)(g_PZ + ej*1024 + h*256 + col0 + 4));
            float zi[8] = {zi0.x, zi0.y, zi0.z, zi0.w, zi1.x, zi1.y, zi1.z, zi1.w};
            float zj[8] = {zj0.x, zj0.y, zj0.z, zj0.w, zj1.x, zj1.y, zj1.z, zj1.w};
            float qi[8] = {qi0.x, qi0.y, qi0.z, qi0.w, qi1.x, qi1.y, qi1.z, qi1.w};
            float qj[8] = {qj0.x, qj0.y, qj0.z, qj0.w, qj1.x, qj1.y, qj1.z, qj1.w};
            #pragma unroll
            for (int i = 0; i < 8; i++) {
                acc0[i] = fmaf(a0s[0][h], zi[i], fmaf(a1s[0][h], zj[i], acc0[i]));
                acc1[i] = fmaf(a0s[1][h], zi[i], fmaf(a1s[1][h], zj[i], acc1[i]));
                ap0[i]  = fmaf(a0s[0][h], qi[i], fmaf(a1s[0][h], qj[i], ap0[i]));
                ap1[i]  = fmaf(a0s[1][h], qi[i], fmaf(a1s[1][h], qj[i], ap1[i]));
            }
        }
        #define TOKEN_FINISH(ACC, AP, ROW)                                           \
        do {                                                                         \
            float s1 = 0.f, s2 = 0.f;                                                \
            _Pragma("unroll")                                                        \
            for (int i = 0; i < 8; i++) { s1 += ACC[i]; s2 += ACC[i]*ACC[i]; }       \
            _Pragma("unroll")                                                        \
            for (int off = 16; off; off >>= 1) {                                     \
                s1 += __shfl_xor_sync(0xffffffffu, s1, off);                         \
                s2 += __shfl_xor_sync(0xffffffffu, s2, off);                         \
            }                                                                        \
            float m   = s1 * (1.f/256.f);                                            \
            float var = s2 * (1.f/256.f) - m*m;                                      \
            float inv1 = rsqrtf(var + 1e-5f);                                        \
            float h2v[8];                                                            \
            float t1 = 0.f, t2s = 0.f;                                               \
            _Pragma("unroll")                                                        \
            for (int i = 0; i < 8; i++) {                                            \
                int col = col0 + i;                                                  \
                float h1 = (ACC[i] - m)*inv1*__ldg(ln1_s + col) + __ldg(ln1_b + col);\
                float t2v = inv1*(AP[i] - m*__ldg(g_c2 + col)) + __ldg(g_c3 + col);  \
                float h2 = h1 + tanhf(t2v + __ldg(b2 + col));                        \
                h2v[i] = h2; t1 += h2; t2s += h2*h2;                                 \
            }                                                                        \
            _Pragma("unroll")                                                        \
            for (int off = 16; off; off >>= 1) {                                     \
                t1 += __shfl_xor_sync(0xffffffffu, t1, off);                         \
                t2s += __shfl_xor_sync(0xffffffffu, t2s, off);                       \
            }                                                                        \
            float m2   = t1 * (1.f/256.f);                                           \
            float var2 = t2s * (1.f/256.f) - m2*m2;                                  \
            float inv2 = rsqrtf(var2 + 1e-5f);                                       \
            _Pragma("unroll")                                                        \
            for (int i = 0; i < 8; i++) {                                            \
                int col = col0 + i;                                                  \
                float y = (h2v[i] - m2)*inv2*__ldg(ln2_s + col) + __ldg(ln2_b + col);\
                sst(Hh + (ROW)*RS + col, Hl + (ROW)*RS + col, y);                    \
            }                                                                        \
        } while (0)
        TOKEN_FINISH(acc0, ap0, pr*2);
        TOKEN_FINISH(acc1, ap1, pr*2 + 1);
        #undef TOKEN_FINISH
    }
    __syncthreads();

    // ---- layer 1 Q, K GEMMs -> registers ----
    float CQ[2][4][4], CK[2][4][4];
    mma_gemm(g_Ws_hi + 1*65536, g_Ws_lo + 1*65536, sHb, sWb, CQ, tid);
    gemm_prefetch(g_Ws_hi + 2*65536, g_Ws_lo + 2*65536, sWb, tid);
    frag_add_bias(CQ, bq + 256, lane, warp);
    mma_gemm(g_Ws_hi + 2*65536, g_Ws_lo + 2*65536, sHb, sWb, CK, tid);
    gemm_prefetch(g_Ws_hi + 3*65536, g_Ws_lo + 3*65536, sWb, tid);
    frag_add_bias(CK, bk + 256, lane, warp);

    // ---- logits in registers: partner rows via shfl_xor(.,4) ----
    {
        float ls[2][2] = {{0.f,0.f},{0.f,0.f}};
        float lc[2][2] = {{0.f,0.f},{0.f,0.f}};
        #pragma unroll
        for (int mi = 0; mi < 2; mi++)
            #pragma unroll
            for (int ni = 0; ni < 4; ni++)
                #pragma unroll
                for (int hf = 0; hf < 2; hf++) {
                    float q0 = CQ[mi][ni][hf*2], q1 = CQ[mi][ni][hf*2+1];
                    float k0 = CK[mi][ni][hf*2], k1 = CK[mi][ni][hf*2+1];
                    float k0p = __shfl_xor_sync(0xffffffffu, k0, 4);
                    float k1p = __shfl_xor_sync(0xffffffffu, k1, 4);
                    ls[mi][hf] = fmaf(q0, k0, fmaf(q1, k1, ls[mi][hf]));
                    lc[mi][hf] = fmaf(q0, k0p, fmaf(q1, k1p, lc[mi][hf]));
                }
        #pragma unroll
        for (int mi = 0; mi < 2; mi++)
            #pragma unroll
            for (int hf = 0; hf < 2; hf++) {
                float a = ls[mi][hf], b = lc[mi][hf];
                a += __shfl_xor_sync(0xffffffffu, a, 1);
                a += __shfl_xor_sync(0xffffffffu, a, 2);
                b += __shfl_xor_sync(0xffffffffu, b, 1);
                b += __shfl_xor_sync(0xffffffffu, b, 2);
                if ((lane & 3) == 0) {
                    int row = mi*16 + hf*8 + (lane >> 2);
                    int head = warp >> 1;
                    atomicAdd(&s_part[row][head][0], a);
                    atomicAdd(&s_part[row][head][1], b);
                }
            }
    }
    __syncthreads();

    // ---- softmax: 128 items (row, head) ----
    if (tid < MTOK*4) {
        int row = tid >> 2, h = tid & 3;
        int p = row >> 1, s = row & 1;
        float lss = s_part[row][h][0] * 0.125f;
        float lcr = s_part[row][h][1] * 0.125f;
        float l0 = s ? lcr : lss;
        float l1 = s ? lss : lcr;
        float mx = fmaxf(l0, l1);
        float e0 = expf(l0 - mx), e1 = expf(l1 - mx);
        float inv = 1.f / (e0 + e1);
        s_attn[p][h][s][0] = e0 * inv;
        s_attn[p][h][s][1] = e1 * inv;
    }
    __syncthreads();

    // ---- V GEMM -> registers; o combine in registers -> O planes ----
    {
        float CV[2][4][4];
        mma_gemm(g_Ws_hi + 3*65536, g_Ws_lo + 3*65536, sHb, sWb, CV, tid);
        gemm_prefetch(g_Ws_hi + 4*65536, g_Ws_lo + 4*65536, sWb, tid);
        frag_add_bias(CV, bv + 256, lane, warp);
        int head = warp >> 1;
        #pragma unroll
        for (int mi = 0; mi < 2; mi++)
            #pragma unroll
            for (int hf = 0; hf < 2; hf++) {
                int row = mi*16 + hf*8 + (lane >> 2);
                int p = row >> 1, s = row & 1;
                float a0 = s_attn[p][head][s][0], a1 = s_attn[p][head][s][1];
                #pragma unroll
                for (int ni = 0; ni < 4; ni++) {
                    float v0v = CV[mi][ni][hf*2], v1v = CV[mi][ni][hf*2+1];
                    float v0p = __shfl_xor_sync(0xffffffffu, v0v, 4);
                    float v1p = __shfl_xor_sync(0xffffffffu, v1v, 4);
                    float ve0 = s ? v0p : v0v;
                    float vo0 = s ? v0v : v0p;
                    float ve1 = s ? v1p : v1v;
                    float vo1 = s ? v1v : v1p;
                    int col = warp*32 + ni*8 + (lane & 3)*2;
                    sst(Oh + row*RS + col,     Ol + row*RS + col,     a0*ve0 + a1*vo0);
                    sst(Oh + row*RS + col + 1, Ol + row*RS + col + 1, a0*ve1 + a1*vo1);
                }
            }
    }
    __syncthreads();

    float C[2][4][4];

    // ---- h = LN1_1( h2 + o @ WoW1_1 + boW1_1 ) ----
    mma_gemm(g_Ws_hi + 4*65536, g_Ws_lo + 4*65536, sOb, sWb, C, tid);
    gemm_prefetch(g_Ws_hi + 5*65536, g_Ws_lo + 5*65536, sWb, tid);
    #pragma unroll
    for (int ni = 0; ni < 4; ni++) {
        int col = warp*32 + ni*8 + (lane & 3)*2;
        float v0 = __ldg(g_boW1 + 256 + col), v1 = __ldg(g_boW1 + 256 + col + 1);
        #pragma unroll
        for (int mi = 0; mi < 2; mi++)
            #pragma unroll
            for (int hf = 0; hf < 2; hf++) {
                int row = mi*16 + (lane >> 2) + hf*8;
                float h0v = rec(Hh, Hl, row*RS + col)     + C[mi][ni][hf*2]   + v0;
                float h1v = rec(Hh, Hl, row*RS + col + 1) + C[mi][ni][hf*2+1] + v1;
                sst(Hh + row*RS + col,     Hl + row*RS + col,     h0v);
                sst(Hh + row*RS + col + 1, Hl + row*RS + col + 1, h1v);
            }
    }
    __syncthreads();
    lnorm(Hh, Hl, ln1_s + 256, ln1_b + 256, tid);
    __syncthreads();

    // ---- h = LN2_1( h + tanh(h @ W2_1 + b2_1) ) ----
    mma_gemm(g_Ws_hi + 5*65536, g_Ws_lo + 5*65536, sHb, sWb, C, tid);
    #pragma unroll
    for (int ni = 0; ni < 4; ni++) {
        int col = warp*32 + ni*8 + (lane & 3)*2;
        float v0 = __ldg(b2 + 256 + col), v1 = __ldg(b2 + 256 + col + 1);
        #pragma unroll
        for (int mi = 0; mi < 2; mi++)
            #pragma unroll
            for (int hf = 0; hf < 2; hf++) {
                int row = mi*16 + (lane >> 2) + hf*8;
                float h0v = rec(Hh, Hl, row*RS + col)     + tanhf(C[mi][ni][hf*2]   + v0);
                float h1v = rec(Hh, Hl, row*RS + col + 1) + tanhf(C[mi][ni][hf*2+1] + v1);
                sst(Hh + row*RS + col,     Hl + row*RS + col,     h0v);
                sst(Hh + row*RS + col + 1, Hl + row*RS + col + 1, h1v);
            }
    }
    __syncthreads();
    lnorm(Hh, Hl, ln2_s + 256, ln2_b + 256, tid);
    __syncthreads();

    // ---- orbital projections: 8 warps = 8 combos, all pairs ----
    {
        int combo = warp;
        const float* Ws = (combo >= 4) ? Worb_i : Worb_r;
        int s = (combo >> 1) & 1, c = combo & 1;
        #pragma unroll 1
        for (int p = 0; p < PPB; p++) {
            float sum = 0.f;
            int hb = (p*2+s)*RS;
            #pragma unroll
            for (int k = 0; k < 8; k++) {
                int d = lane + 32*k;
                sum = fmaf(rec(Hh, Hl, hb + d), __ldg(Ws + d*2 + c), sum);
            }
            #pragma unroll
            for (int off = 16; off; off >>= 1) sum += __shfl_xor_sync(0xffffffffu, sum, off);
            if (lane == 0) s_orb[p][combo] = sum;
        }
    }
    __syncthreads();

    if (tid < PPB) {
        int p = tid;
        float th0 = s_tp[p][0][0], ph0 = s_tp[p][0][1];
        float th1 = s_tp[p][1][0], ph1 = s_tp[p][1][1];
        float c0, s0, c1, s1;
        sincosf(0.5f*th0, &s0, &c0);
        sincosf(0.5f*th1, &s1, &c1);
        float hd = 0.5f*(ph0 - ph1);
        float chd, shd; sincosf(hd, &shd, &chd);
        float re = (c0*s1 - c1*s0) * chd;
        float im = (c0*s1 + c1*s0) * shd;
        float chord2 = re*re + im*im;
        float trunc = 1.f - expf(-100.f * chord2);
        float t2 = trunc * trunc;
        float a_r = s_orb[p][0], b_r = s_orb[p][1], c_r = s_orb[p][2], d_r = s_orb[p][3];
        float a_i = s_orb[p][4], b_i = s_orb[p][5], c_i = s_orb[p][6], d_i = s_orb[p][7];
        float det_r = (a_r*d_r - a_i*d_i) - (b_r*c_r - b_i*c_i);
        float det_i = (a_r*d_i + a_i*d_r) - (b_r*c_i + b_i*c_r);
        det_r *= t2; det_i *= t2;
        int i = s_ij[p][0], j = s_ij[p][1];
        g_A[i*NE + j] = make_float2(det_r, det_i);
        g_A[j*NE + i] = make_float2(-det_r, -det_i);
    }
}

// ---------------- cusp matrix + bosonic log sum ---------------------------
__global__ void cusp_bos_kernel(const float* __restrict__ electrons)
{
    int i = blockIdx.x, j = threadIdx.x;
    __shared__ double s_red[2][8];
    float thi = electrons[2*i], phi_ = electrons[2*i+1];
    float thj = electrons[2*j], phj  = electrons[2*j+1];
    float ci, si, cj, sj;
    sincosf(0.5f*thi, &si, &ci);
    sincosf(0.5f*thj, &sj, &cj);
    float hd = 0.5f*(phi_ - phj);
    float chd, shd; sincosf(hd, &shd, &chd);
    float er = (ci*sj - si*cj) * chd;
    float ei = (ci*sj + si*cj) * shd;

    float eye = (i == j) ? 1.f : 0.f;
    float cr = er + eye, cim = ei;
    float rc2 = cr*cr + cim*cim;
    float g = expf(-100.f * rc2);
    float2 a = (i == j) ? make_float2(0.f, 0.f) : g_A[i*NE + j];
    a.x += cr * g;
    a.y += cim * g;
    g_A[i*NE + j] = a;

    double lr = 0.0, li = 0.0;
    if (i != j) {
        float rho2 = er*er + ei*ei;
        lr = 0.5 * log((double)(0.01f + rho2));
        li = (double)atan2f(ei, er);
    }
    int lane = j & 31, wrp = j >> 5;
    #pragma unroll
    for (int off = 16; off; off >>= 1) {
        lr += __shfl_xor_sync(0xffffffffu, lr, off);
        li += __shfl_xor_sync(0xffffffffu, li, off);
    }
    if (lane == 0) { s_red[0][wrp] = lr; s_red[1][wrp] = li; }
    __syncthreads();
    if (j == 0) {
        double a0 = 0.0, a1 = 0.0;
        #pragma unroll
        for (int w = 0; w < 8; w++) { a0 += s_red[0][w]; a1 += s_red[1][w]; }
        atomicAdd(&g_acc[0], a0);
        atomicAdd(&g_acc[1], a1);
    }
}

// ---------------- complex LU with partial pivoting (slogdet) --------------
__device__ __forceinline__ float2 cmul(float2 a, float2 b) {
    return make_float2(a.x*b.x - a.y*b.y, a.x*b.y + a.y*b.x);
}

__global__ void __launch_bounds__(1024) lu_kernel()
{
    __shared__ float2 s_prow[256];
    __shared__ float2 s_l[256];
    __shared__ float  s_mx[8];
    __shared__ int    s_mi[8];
    __shared__ float2 s_inv;
    __shared__ int    s_piv;
    int tid = threadIdx.x;
    double logabs = 0.0, argsum = 0.0;
    int par = 0;

    for (int k = 0; k < 256; k++) {
        if (tid < 256) {
            float v = -1.f; int idx = tid;
            if (tid >= k) { float2 a = g_A[tid*256 + k]; v = fabsf(a.x) + fabsf(a.y); }
            #pragma unroll
            for (int off = 16; off; off >>= 1) {
                float ov = __shfl_xor_sync(0xffffffffu, v, off);
                int   oi = __shfl_xor_sync(0xffffffffu, idx, off);
                if (ov > v) { v = ov; idx = oi; }
            }
            if ((tid & 31) == 0) { s_mx[tid>>5] = v; s_mi[tid>>5] = idx; }
        }
        __syncthreads();
        if (tid == 0) {
            float bv = -1.f; int bi = k;
            #pragma unroll
            for (int w = 0; w < 8; w++) if (s_mx[w] > bv) { bv = s_mx[w]; bi = s_mi[w]; }
            s_piv = bi;
        }
        __syncthreads();
        int pv = s_piv;
        if (pv != k && tid < 256) {
            float2 t = g_A[k*256 + tid];
            g_A[k*256 + tid] = g_A[pv*256 + tid];
            g_A[pv*256 + tid] = t;
        }
        __syncthreads();
        if (tid == 0) {
            if (pv != k) par ^= 1;
            float2 u = g_A[k*256 + k];
            double n2 = (double)u.x*u.x + (double)u.y*u.y;
            logabs += 0.5 * log(n2);
            argsum += atan2((double)u.y, (double)u.x);
            float d = u.x*u.x + u.y*u.y;
            s_inv = make_float2(u.x/d, -u.y/d);
        }
        __syncthreads();
        if (tid < 256) {
            s_prow[tid] = g_A[k*256 + tid];
            if (tid > k) {
                float2 l = cmul(g_A[tid*256 + k], s_inv);
                s_l[tid] = l;
                g_A[tid*256 + k] = l;
            }
        }
        __syncthreads();
        {
            int c = tid & 255, r0 = tid >> 8;
            if (c > k) {
                float2 pr = s_prow[c];
                #pragma unroll 4
                for (int i = k + 1 + r0; i < 256; i += 4) {
                    float2 l = s_l[i];
                    float2 a = g_A[i*256 + c];
                    a.x -= l.x*pr.x - l.y*pr.y;
                    a.y -= l.x*pr.y + l.y*pr.x;
                    g_A[i*256 + c] = a;
                }
            }
        }
        __syncthreads();
    }
    if (tid == 0) { g_lu_logabs = logabs; g_lu_arg = argsum; g_lu_par = par; }
}

// ---------------- init + finalize -----------------------------------------
__global__ void init_kernel() { g_acc[0] = 0.0; g_acc[1] = 0.0; }

__global__ void finalize_kernel(float* out)
{
    const double PI = 3.14159265358979323846;
    double logabs = g_lu_logabs;
    double arg = g_lu_arg + (g_lu_par ? PI : 0.0);
    double w = fmod(arg, 2.0*PI);
    if (w >  PI) w -= 2.0*PI;
    if (w <= -PI) w += 2.0*PI;
    out[0] = (float)(0.5*logabs + g_acc[0]);
    out[1] = (float)(0.5*w      + g_acc[1]);
}

// ---------------- launch ---------------------------------------------------
extern "C" void kernel_launch(void* const* d_in, const int* in_sizes, int n_in,
                              void* d_out, int out_size)
{
    const float* electrons = (const float*)d_in[0];
    const float* W_in   = (const float*)d_in[1];
    const float* Wq     = (const float*)d_in[2];
    const float* bq     = (const float*)d_in[3];
    const float* Wk     = (const float*)d_in[4];
    const float* bk     = (const float*)d_in[5];
    const float* Wv     = (const float*)d_in[6];
    const float* bv     = (const float*)d_in[7];
    const float* Wo     = (const float*)d_in[8];
    const float* bo     = (const float*)d_in[9];
    const float* W1     = (const float*)d_in[10];
    const float* ln1_s  = (const float*)d_in[11];
    const float* ln1_b  = (const float*)d_in[12];
    const float* W2     = (const float*)d_in[13];
    const float* b2     = (const float*)d_in[14];
    const float* ln2_s  = (const float*)d_in[15];
    const float* ln2_b  = (const float*)d_in[16];
    const float* Worb_r = (const float*)d_in[17];
    const float* Worb_i = (const float*)d_in[18];

    cudaFuncSetAttribute(pair_kernel, cudaFuncAttributeMaxDynamicSharedMemorySize, SMEM_BYTES);

    wow1_kernel<<<2*257, 256>>>(Wo, W1, bo);
    prep_kernel<<<256, 256>>>(electrons, W_in, Wq, bq, Wk, bk, Wv, bv);
    gram_z_kernel<<<256, 256>>>();
    pbasis_kernel<<<1281, 256>>>(W2, ln1_s, ln1_b);
    convert_host<<<4*256, 256>>>(Wq, Wk, Wv, W2);
    convert_wow1<<<256, 256>>>();
    init_kernel<<<1, 1>>>();
    pair_kernel<<<NBLOCKS, NTHREADS, SMEM_BYTES>>>(electrons, bq, bk, bv,
                                                   ln1_s, ln1_b, b2, ln2_s, ln2_b,
                                                   Worb_r, Worb_i);
    cusp_bos_kernel<<<NE, NE>>>(electrons);
    lu_kernel<<<1, 1024>>>();
    finalize_kernel<<<1, 1>>>((float*)d_out);
}

// round 16
// speedup vs baseline: 1.0471x; 1.0471x over previous
#include <cuda_runtime.h>
#include <cuda_bf16.h>
#include <math.h>
#include <cstdint>

#define NE  256
#define P_TOTAL 32640
#define PPB 16
#define MTOK 32                        /* 2*PPB tokens per CTA */
#define NBLOCKS (P_TOTAL/PPB)          /* 2040 */
#define NTHREADS 256
#define RS  264                        /* padded row stride, bf16 elems */
#define RSB (RS*2)                     /* 528 bytes */
#define PL  (MTOK*RS)                  /* one activation plane, halves */
#define PLB (PL*2)                     /* plane bytes (16896) */
#define WCHB (64*RS*2)                 /* W chunk hi+lo rows: 33792 bytes */
#define SMEM_BYTES (2*PLB + WCHB)      /* 33792 + 33792 = 67584 */

// ---------------- device globals (no allocations) --------------------------
// split-bf16 weights: slots 1=Wq_1, 2=Wk_1, 3=Wvw (Wv_1@WoW1_1), 5=W2_1
__device__ __nv_bfloat16 g_Ws_hi[6*65536];
__device__ __nv_bfloat16 g_Ws_lo[6*65536];
__device__ __align__(16) float g_h0[65536];
__device__ __align__(16) float g_q0[65536], g_k0[65536], g_v0[65536];
__device__ __align__(16) float g_G[4*65536];
__device__ __align__(16) float g_Z[65536*4];
__device__ __align__(16) float g_WoW1[2*65536];
__device__ __align__(16) float g_boW1[2*256];
__device__ __align__(16) float g_bvwbo[256];   // bv_1@WoW1_1 + bo_1@W1_1
__device__ __align__(16) float g_Ph0[65536];
__device__ __align__(16) float g_PZ[65536*4];
__device__ __align__(16) float g_c1[256], g_c2[256], g_c3[256];
__device__ float2 g_A[NE*NE];
__device__ double g_acc[2];
__device__ double g_lu_logabs, g_lu_arg;
__device__ int    g_lu_par;

// ---------------- helpers ---------------------------------------------------
__device__ __forceinline__ uint32_t smem_u32(const void* p) {
    return (uint32_t)__cvta_generic_to_shared(p);
}
__device__ __forceinline__ void sst(__nv_bfloat16* h, __nv_bfloat16* l, float x) {
    __nv_bfloat16 hi = __float2bfloat16_rn(x);
    *h = hi;
    *l = __float2bfloat16_rn(x - __bfloat162float(hi));
}
__device__ __forceinline__ float rec(const __nv_bfloat16* h, const __nv_bfloat16* l, int idx) {
    return __bfloat162float(h[idx]) + __bfloat162float(l[idx]);
}

// ---------------- precompute kernels ---------------------------------------
__global__ void wow1_kernel(const float* __restrict__ Wo, const float* __restrict__ W1,
                            const float* __restrict__ bo)
{
    int b = blockIdx.x, col = threadIdx.x;
    int l = b / 257, r = b % 257;
    const float* W1l = W1 + l*65536;
    float acc = 0.f;
    if (r < 256) {
        const float* Wol = Wo + l*65536 + r*256;
        for (int d = 0; d < 256; d++) acc = fmaf(Wol[d], W1l[d*256 + col], acc);
        g_WoW1[l*65536 + r*256 + col] = acc;
    } else {
        const float* bol = bo + l*256;
        for (int d = 0; d < 256; d++) acc = fmaf(bol[d], W1l[d*256 + col], acc);
        g_boW1[l*256 + col] = acc;
    }
}

// slot 3 = split(Wv_1 @ WoW1_1); g_bvwbo = bv_1 @ WoW1_1 + boW1_1
__global__ void wvw_kernel(const float* __restrict__ Wv, const float* __restrict__ bv)
{
    __shared__ float src[256];
    int b = blockIdx.x, col = threadIdx.x;
    const float* W = g_WoW1 + 65536;
    if (b < 256) {
        src[col] = __ldg(Wv + 65536 + b*256 + col);
        __syncthreads();
        float acc = 0.f;
        for (int m = 0; m < 256; m++) acc = fmaf(src[m], __ldg(W + m*256 + col), acc);
        __nv_bfloat16 hi = __float2bfloat16_rn(acc);
        g_Ws_hi[3*65536 + b*256 + col] = hi;
        g_Ws_lo[3*65536 + b*256 + col] = __float2bfloat16_rn(acc - __bfloat162float(hi));
    } else {
        src[col] = __ldg(bv + 256 + col);
        __syncthreads();
        float acc = 0.f;
        for (int m = 0; m < 256; m++) acc = fmaf(src[m], __ldg(W + m*256 + col), acc);
        g_bvwbo[col] = acc + g_boW1[256 + col];
    }
}

__global__ void prep_kernel(const float* __restrict__ electrons, const float* __restrict__ W_in,
                            const float* __restrict__ Wq, const float* __restrict__ bq,
                            const float* __restrict__ Wk, const float* __restrict__ bk,
                            const float* __restrict__ Wv, const float* __restrict__ bv)
{
    __shared__ float hrow[256];
    int e = blockIdx.x, col = threadIdx.x;
    float th = electrons[2*e], ph = electrons[2*e+1];
    float st, ct, sp, cp;
    sincosf(th, &st, &ct);
    sincosf(ph, &sp, &cp);
    float f0 = ct, f1 = st*cp, f2 = st*sp;
    float h = f0*__ldg(W_in + col) + f1*__ldg(W_in + 256 + col) + f2*__ldg(W_in + 512 + col);
    g_h0[e*256 + col] = h;
    hrow[col] = h;
    __syncthreads();
    float q = __ldg(bq + col), k = __ldg(bk + col), v = __ldg(bv + col);
    for (int d = 0; d < 256; d++) {
        float hv = hrow[d];
        q = fmaf(hv, __ldg(Wq + d*256 + col), q);
        k = fmaf(hv, __ldg(Wk + d*256 + col), k);
        v = fmaf(hv, __ldg(Wv + d*256 + col), v);
    }
    g_q0[e*256 + col] = q;
    g_k0[e*256 + col] = k;
    g_v0[e*256 + col] = v;
}

__global__ void gram_z_kernel()
{
    __shared__ float qrow[256], vrow[256];
    int i = blockIdx.x, t = threadIdx.x;
    qrow[t] = g_q0[i*256 + t];
    vrow[t] = g_v0[i*256 + t];
    __syncthreads();
    #pragma unroll
    for (int h = 0; h < 4; h++) {
        float acc = 0.f;
        const float* krow = g_k0 + t*256 + h*64;
        #pragma unroll 8
        for (int d = 0; d < 64; d++) acc = fmaf(qrow[h*64 + d], __ldg(krow + d), acc);
        g_G[h*65536 + i*256 + t] = acc * 0.125f;
    }
    #pragma unroll
    for (int h = 0; h < 4; h++) {
        float acc = 0.f;
        #pragma unroll 8
        for (int d = 0; d < 64; d++)
            acc = fmaf(vrow[h*64 + d], __ldg(g_WoW1 + (h*64 + d)*256 + t), acc);
        g_Z[i*1024 + h*256 + t] = acc;
    }
}

__global__ void pbasis_kernel(const float* __restrict__ W2, const float* __restrict__ ln1_s,
                              const float* __restrict__ ln1_b)
{
    __shared__ float src[256];
    int b = blockIdx.x, col = threadIdx.x;
    if (b < 256) {
        src[col] = g_h0[b*256 + col] * __ldg(ln1_s + col);
        __syncthreads();
        float acc = 0.f;
        for (int d = 0; d < 256; d++) acc = fmaf(src[d], __ldg(W2 + d*256 + col), acc);
        g_Ph0[b*256 + col] = acc;
    } else if (b < 1280) {
        int idx = b - 256;
        src[col] = g_Z[idx*256 + col] * __ldg(ln1_s + col);
        __syncthreads();
        float acc = 0.f;
        for (int d = 0; d < 256; d++) acc = fmaf(src[d], __ldg(W2 + d*256 + col), acc);
        g_PZ[idx*256 + col] = acc;
    } else {
        src[col] = g_boW1[col] * __ldg(ln1_s + col);
        __syncthreads();
        float a1 = 0.f, a2 = 0.f, a3 = 0.f;
        for (int d = 0; d < 256; d++) {
            float w = __ldg(W2 + d*256 + col);
            a1 = fmaf(src[d], w, a1);
            a2 = fmaf(__ldg(ln1_s + d), w, a2);
            a3 = fmaf(__ldg(ln1_b + d), w, a3);
        }
        g_c1[col] = a1; g_c2[col] = a2; g_c3[col] = a3;
    }
}

// split host weights: m 0..2 -> {Wq_1->1, Wk_1->2, W2_1->5}
__global__ void convert_host(const float* __restrict__ Wq, const float* __restrict__ Wk,
                             const float* __restrict__ W2)
{
    int idx = blockIdx.x * 256 + threadIdx.x;
    int m = idx >> 16, off = idx & 65535;
    const float* src; int slot;
    switch (m) {
        case 0: src = Wq + 65536;  slot = 1; break;
        case 1: src = Wk + 65536;  slot = 2; break;
        default: src = W2 + 65536; slot = 5; break;
    }
    float v = src[off];
    __nv_bfloat16 hi = __float2bfloat16_rn(v);
    g_Ws_hi[slot*65536 + off] = hi;
    g_Ws_lo[slot*65536 + off] = __float2bfloat16_rn(v - __bfloat162float(hi));
}

// ---------------- split-bf16 GEMM (R14: 32-row chunks, single buffer) -------
__device__ __forceinline__ void cp_load_chunk(const __nv_bfloat16* __restrict__ gWhi,
                                              const __nv_bfloat16* __restrict__ gWlo,
                                              int chunk, uint32_t sWbuf, int tid)
{
    #pragma unroll
    for (int i = 0; i < 8; i++) {
        int g = tid + i*NTHREADS;             // 2048 granules of 16B
        int plane = g >> 10;
        int row = (g >> 5) & 31, c16 = g & 31;
        uint32_t s = sWbuf + (plane*32 + row)*RSB + c16*16;
        const __nv_bfloat16* base = plane ? gWlo : gWhi;
        const void* gp = base + (chunk*32 + row)*256 + c16*8;
        asm volatile("cp.async.cg.shared.global [%0],[%1],16;\n" :: "r"(s), "l"(gp));
    }
    asm volatile("cp.async.commit_group;\n");
}

__device__ __forceinline__ void mma_gemm(const __nv_bfloat16* __restrict__ gWhi,
                                         const __nv_bfloat16* __restrict__ gWlo,
                                         uint32_t sA, uint32_t sW,
                                         float C[2][4][4], int tid)
{
    int lane = tid & 31, warp = tid >> 5;
    #pragma unroll
    for (int a = 0; a < 2; a++)
        #pragma unroll
        for (int b = 0; b < 4; b++)
            #pragma unroll
            for (int d = 0; d < 4; d++) C[a][b][d] = 0.f;

    #pragma unroll 1
    for (int c = 0; c < 8; c++) {
        cp_load_chunk(gWhi, gWlo, c, sW, tid);
        asm volatile("cp.async.wait_group 0;\n");
        __syncthreads();
        #pragma unroll
        for (int ks = 0; ks < 2; ks++) {
            int k0 = c*32 + ks*16;
            uint32_t ahi[2][4], alo[2][4], bhi[2][4], blo[2][4];
            #pragma unroll
            for (int mi = 0; mi < 2; mi++) {
                uint32_t addr = sA + (mi*16 + (lane & 15))*RSB + (k0 + ((lane >> 4) << 3))*2;
                asm volatile("ldmatrix.sync.aligned.m8n8.x4.shared.b16 {%0,%1,%2,%3},[%4];\n"
                    : "=r"(ahi[mi][0]), "=r"(ahi[mi][1]), "=r"(ahi[mi][2]), "=r"(ahi[mi][3]) : "r"(addr));
                asm volatile("ldmatrix.sync.aligned.m8n8.x4.shared.b16 {%0,%1,%2,%3},[%4];\n"
                    : "=r"(alo[mi][0]), "=r"(alo[mi][1]), "=r"(alo[mi][2]), "=r"(alo[mi][3]) : "r"(addr + PLB));
            }
            #pragma unroll
            for (int nh = 0; nh < 2; nh++) {
                uint32_t addr = sW + (ks*16 + (lane & 15))*RSB
                              + (warp*32 + nh*16 + ((lane >> 4) << 3))*2;
                asm volatile("ldmatrix.sync.aligned.m8n8.x4.trans.shared.b16 {%0,%1,%2,%3},[%4];\n"
                    : "=r"(bhi[nh][0]), "=r"(bhi[nh][1]), "=r"(bhi[nh][2]), "=r"(bhi[nh][3]) : "r"(addr));
                asm volatile("ldmatrix.sync.aligned.m8n8.x4.trans.shared.b16 {%0,%1,%2,%3},[%4];\n"
                    : "=r"(blo[nh][0]), "=r"(blo[nh][1]), "=r"(blo[nh][2]), "=r"(blo[nh][3]) : "r"(addr + 32*RSB));
            }
            #pragma unroll
            for (int mi = 0; mi < 2; mi++)
                #pragma unroll
                for (int ni = 0; ni < 4; ni++) {
                    uint32_t bh0 = bhi[ni>>1][(ni&1)*2], bh1 = bhi[ni>>1][(ni&1)*2 + 1];
                    uint32_t bl0 = blo[ni>>1][(ni&1)*2], bl1 = blo[ni>>1][(ni&1)*2 + 1];
                    asm volatile("mma.sync.aligned.m16n8k16.row.col.f32.bf16.bf16.f32 "
                        "{%0,%1,%2,%3},{%4,%5,%6,%7},{%8,%9},{%0,%1,%2,%3};\n"
                        : "+f"(C[mi][ni][0]), "+f"(C[mi][ni][1]),
                          "+f"(C[mi][ni][2]), "+f"(C[mi][ni][3])
                        : "r"(ahi[mi][0]), "r"(ahi[mi][1]), "r"(ahi[mi][2]), "r"(ahi[mi][3]),
                          "r"(bh0), "r"(bh1));
                    asm volatile("mma.sync.aligned.m16n8k16.row.col.f32.bf16.bf16.f32 "
                        "{%0,%1,%2,%3},{%4,%5,%6,%7},{%8,%9},{%0,%1,%2,%3};\n"
                        : "+f"(C[mi][ni][0]), "+f"(C[mi][ni][1]),
                          "+f"(C[mi][ni][2]), "+f"(C[mi][ni][3])
                        : "r"(alo[mi][0]), "r"(alo[mi][1]), "r"(alo[mi][2]), "r"(alo[mi][3]),
                          "r"(bh0), "r"(bh1));
                    asm volatile("mma.sync.aligned.m16n8k16.row.col.f32.bf16.bf16.f32 "
                        "{%0,%1,%2,%3},{%4,%5,%6,%7},{%8,%9},{%0,%1,%2,%3};\n"
                        : "+f"(C[mi][ni][0]), "+f"(C[mi][ni][1]),
                          "+f"(C[mi][ni][2]), "+f"(C[mi][ni][3])
                        : "r"(ahi[mi][0]), "r"(ahi[mi][1]), "r"(ahi[mi][2]), "r"(ahi[mi][3]),
                          "r"(bl0), "r"(bl1));
                }
        }
        __syncthreads();
    }
}

__device__ __forceinline__ void frag_add_bias(float C[2][4][4], const float* __restrict__ b,
                                              int lane, int warp)
{
    #pragma unroll
    for (int ni = 0; ni < 4; ni++) {
        int col = warp*32 + ni*8 + (lane & 3)*2;
        float v0 = __ldg(b + col), v1 = __ldg(b + col + 1);
        #pragma unroll
        for (int mi = 0; mi < 2; mi++)
            #pragma unroll
            for (int hf = 0; hf < 2; hf++) {
                C[mi][ni][hf*2]   += v0;
                C[mi][ni][hf*2+1] += v1;
            }
    }
}

__device__ __forceinline__ void lnorm(__nv_bfloat16* Hh, __nv_bfloat16* Hl,
                                      const float* __restrict__ sc,
                                      const float* __restrict__ bi, int tid)
{
    int lane = tid & 31, warp = tid >> 5;
    #pragma unroll 1
    for (int rr = 0; rr < 4; rr++) {
        int row = warp*4 + rr;
        float xs[8];
        float s1 = 0.f, s2 = 0.f;
        #pragma unroll
        for (int i = 0; i < 8; i++) {
            int col = lane*8 + i;
            float f = rec(Hh, Hl, row*RS + col);
            xs[i] = f;
            s1 += f; s2 += f*f;
        }
        #pragma unroll
        for (int off = 16; off; off >>= 1) {
            s1 += __shfl_xor_sync(0xffffffffu, s1, off);
            s2 += __shfl_xor_sync(0xffffffffu, s2, off);
        }
        float m   = s1 * (1.f/256.f);
        float var = s2 * (1.f/256.f) - m*m;
        float inv = rsqrtf(var + 1e-5f);
        #pragma unroll
        for (int i = 0; i < 8; i++) {
            int col = lane*8 + i;
            float y = (xs[i] - m)*inv*__ldg(sc+col) + __ldg(bi+col);
            sst(Hh + row*RS + col, Hl + row*RS + col, y);
        }
    }
}

// ---------------- pair transformer ------------------------------------------
__global__ void __launch_bounds__(NTHREADS, 2) pair_kernel(
    const float* __restrict__ electrons,
    const float* __restrict__ bq, const float* __restrict__ bk,
    const float* __restrict__ ln1_s, const float* __restrict__ ln1_b,
    const float* __restrict__ b2,
    const float* __restrict__ ln2_s, const float* __restrict__ ln2_b,
    const float* __restrict__ Worb_r, const float* __restrict__ Worb_i)
{
    extern __shared__ __nv_bfloat16 smem[];
    __nv_bfloat16* Hh = smem;
    __nv_bfloat16* Hl = Hh + PL;
    uint32_t sHb = smem_u32(Hh);
    uint32_t sWb = smem_u32(Hl + PL);

    __shared__ float s_tp[PPB][2][2];
    __shared__ int   s_ij[PPB][2];
    __shared__ float s_part[MTOK][4][2];
    __shared__ float s_attn[PPB][4][2][2];
    __shared__ float s_orb[PPB][8];

    int tid = threadIdx.x;
    int lane = tid & 31, warp = tid >> 5;

    // ---- pair index decode ----
    if (tid < PPB) {
        long long p = (long long)blockIdx.x * PPB + tid;
        double pd = (double)p;
        int i = (int)floor((2.0*NE - 1.0 - sqrt((2.0*NE-1.0)*(2.0*NE-1.0) - 8.0*pd)) * 0.5);
        if (i < 0) i = 0;
        if (i > NE-2) i = NE-2;
        while (i > 0 && (long long)i*(2*NE-1-i)/2 > p) i--;
        while ((long long)(i+1)*(2*NE-1-(i+1))/2 <= p) i++;
        long long base = (long long)i*(2*NE-1-i)/2;
        int j = (int)(p - base) + i + 1;
        s_ij[tid][0] = i; s_ij[tid][1] = j;
    }
    __syncthreads();
    if (tid < PPB*2) {
        int p = tid >> 1, s = tid & 1;
        int e = s_ij[p][s];
        s_tp[p][s][0] = electrons[2*e];
        s_tp[p][s][1] = electrons[2*e+1];
    }
    {
        float* sp = &s_part[0][0][0];
        if (tid < MTOK*4*2) sp[tid] = 0.f;
    }
    __syncthreads();

    // ---- layer 0 fully analytic -> H planes (8 warps x 2 pairs) ----
    #pragma unroll 1
    for (int pq = 0; pq < 2; pq++) {
        int pr = warp*2 + pq;
        int ei = s_ij[pr][0], ej = s_ij[pr][1];
        float a0s[2][4], a1s[2][4];
        #pragma unroll
        for (int s = 0; s < 2; s++) {
            int self = s ? ej : ei;
            #pragma unroll
            for (int h = 0; h < 4; h++) {
                float l0 = __ldg(g_G + h*65536 + self*256 + ei);
                float l1 = __ldg(g_G + h*65536 + self*256 + ej);
                float mx = fmaxf(l0, l1);
                float e0 = expf(l0 - mx), e1 = expf(l1 - mx);
                float inv = 1.f / (e0 + e1);
                a0s[s][h] = e0 * inv;
                a1s[s][h] = e1 * inv;
            }
        }
        int col0 = lane*8;
        float acc0[8], acc1[8], ap0[8], ap1[8];
        {
            float4 bw0 = __ldg((const float4*)(g_boW1 + col0));
            float4 bw1 = __ldg((const float4*)(g_boW1 + col0 + 4));
            float4 hi0 = __ldg((const float4*)(g_h0 + ei*256 + col0));
            float4 hi1 = __ldg((const float4*)(g_h0 + ei*256 + col0 + 4));
            float4 hj0 = __ldg((const float4*)(g_h0 + ej*256 + col0));
            float4 hj1 = __ldg((const float4*)(g_h0 + ej*256 + col0 + 4));
            acc0[0]=hi0.x+bw0.x; acc0[1]=hi0.y+bw0.y; acc0[2]=hi0.z+bw0.z; acc0[3]=hi0.w+bw0.w;
            acc0[4]=hi1.x+bw1.x; acc0[5]=hi1.y+bw1.y; acc0[6]=hi1.z+bw1.z; acc0[7]=hi1.w+bw1.w;
            acc1[0]=hj0.x+bw0.x; acc1[1]=hj0.y+bw0.y; acc1[2]=hj0.z+bw0.z; acc1[3]=hj0.w+bw0.w;
            acc1[4]=hj1.x+bw1.x; acc1[5]=hj1.y+bw1.y; acc1[6]=hj1.z+bw1.z; acc1[7]=hj1.w+bw1.w;
            float4 c10 = __ldg((const float4*)(g_c1 + col0));
            float4 c11 = __ldg((const float4*)(g_c1 + col0 + 4));
            float4 pi0 = __ldg((const float4*)(g_Ph0 + ei*256 + col0));
            float4 pi1 = __ldg((const float4*)(g_Ph0 + ei*256 + col0 + 4));
            float4 pj0 = __ldg((const float4*)(g_Ph0 + ej*256 + col0));
            float4 pj1 = __ldg((const float4*)(g_Ph0 + ej*256 + col0 + 4));
            ap0[0]=pi0.x+c10.x; ap0[1]=pi0.y+c10.y; ap0[2]=pi0.z+c10.z; ap0[3]=pi0.w+c10.w;
            ap0[4]=pi1.x+c11.x; ap0[5]=pi1.y+c11.y; ap0[6]=pi1.z+c11.z; ap0[7]=pi1.w+c11.w;
            ap1[0]=pj0.x+c10.x; ap1[1]=pj0.y+c10.y; ap1[2]=pj0.z+c10.z; ap1[3]=pj0.w+c10.w;
            ap1[4]=pj1.x+c11.x; ap1[5]=pj1.y+c11.y; ap1[6]=pj1.z+c11.z; ap1[7]=pj1.w+c11.w;
        }
        #pragma unroll
        for (int h = 0; h < 4; h++) {
            float4 zi0 = __ldg((const float4*)(g_Z + ei*1024 + h*256 + col0));
            float4 zi1 = __ldg((const float4*)(g_Z + ei*1024 + h*256 + col0 + 4));
            float4 zj0 = __ldg((const float4*)(g_Z + ej*1024 + h*256 + col0));
            float4 zj1 = __ldg((const float4*)(g_Z + ej*1024 + h*256 + col0 + 4));
            float4 qi0 = __ldg((const float4*)(g_PZ + ei*1024 + h*256 + col0));
            float4 qi1 = __ldg((const float4*)(g_PZ + ei*1024 + h*256 + col0 + 4));
            float4 qj0 = __ldg((const float4*)(g_PZ + ej*1024 + h*256 + col0));
            float4 qj1 = __ldg((const float4*)(g_PZ + ej*1024 + h*256 + col0 + 4));
            float zi[8] = {zi0.x, zi0.y, zi0.z, zi0.w, zi1.x, zi1.y, zi1.z, zi1.w};
            float zj[8] = {zj0.x, zj0.y, zj0.z, zj0.w, zj1.x, zj1.y, zj1.z, zj1.w};
            float qi[8] = {qi0.x, qi0.y, qi0.z, qi0.w, qi1.x, qi1.y, qi1.z, qi1.w};
            float qj[8] = {qj0.x, qj0.y, qj0.z, qj0.w, qj1.x, qj1.y, qj1.z, qj1.w};
            #pragma unroll
            for (int i = 0; i < 8; i++) {
                acc0[i] = fmaf(a0s[0][h], zi[i], fmaf(a1s[0][h], zj[i], acc0[i]));
                acc1[i] = fmaf(a0s[1][h], zi[i], fmaf(a1s[1][h], zj[i], acc1[i]));
                ap0[i]  = fmaf(a0s[0][h], qi[i], fmaf(a1s[0][h], qj[i], ap0[i]));
                ap1[i]  = fmaf(a0s[1][h], qi[i], fmaf(a1s[1][h], qj[i], ap1[i]));
            }
        }
        #define TOKEN_FINISH(ACC, AP, ROW)                                           \
        do {                                                                         \
            float s1 = 0.f, s2 = 0.f;                                                \
            _Pragma("unroll")                                                        \
            for (int i = 0; i < 8; i++) { s1 += ACC[i]; s2 += ACC[i]*ACC[i]; }       \
            _Pragma("unroll")                                                        \
            for (int off = 16; off; off >>= 1) {                                     \
                s1 += __shfl_xor_sync(0xffffffffu, s1, off);                         \
                s2 += __shfl_xor_sync(0xffffffffu, s2, off);                         \
            }                                                                        \
            float m   = s1 * (1.f/256.f);                                            \
            float var = s2 * (1.f/256.f) - m*m;                                      \
            float inv1 = rsqrtf(var + 1e-5f);                                        \
            float h2v[8];                                                            \
            float t1 = 0.f, t2s = 0.f;                                               \
            _Pragma("unroll")                                                        \
            for (int i = 0; i < 8; i++) {                                            \
                int col = col0 + i;                                                  \
                float h1 = (ACC[i] - m)*inv1*__ldg(ln1_s + col) + __ldg(ln1_b + col);\
                float t2v = inv1*(AP[i] - m*__ldg(g_c2 + col)) + __ldg(g_c3 + col);  \
                float h2 = h1 + tanhf(t2v + __ldg(b2 + col));                        \
                h2v[i] = h2; t1 += h2; t2s += h2*h2;                                 \
            }                                                                        \
            _Pragma("unroll")                                                        \
            for (int off = 16; off; off >>= 1) {                                     \
                t1 += __shfl_xor_sync(0xffffffffu, t1, off);                         \
                t2s += __shfl_xor_sync(0xffffffffu, t2s, off);                       \
            }                                                                        \
            float m2   = t1 * (1.f/256.f);                                           \
            float var2 = t2s * (1.f/256.f) - m2*m2;                                  \
            float inv2 = rsqrtf(var2 + 1e-5f);                                       \
            _Pragma("unroll")                                                        \
            for (int i = 0; i < 8; i++) {                                            \
                int col = col0 + i;                                                  \
                float y = (h2v[i] - m2)*inv2*__ldg(ln2_s + col) + __ldg(ln2_b + col);\
                sst(Hh + (ROW)*RS + col, Hl + (ROW)*RS + col, y);                    \
            }                                                                        \
        } while (0)
        TOKEN_FINISH(acc0, ap0, pr*2);
        TOKEN_FINISH(acc1, ap1, pr*2 + 1);
        #undef TOKEN_FINISH
    }
    __syncthreads();

    // ---- layer 1 Q, K GEMMs -> registers ----
    float CQ[2][4][4], CK[2][4][4];
    mma_gemm(g_Ws_hi + 1*65536, g_Ws_lo + 1*65536, sHb, sWb, CQ, tid);
    frag_add_bias(CQ, bq + 256, lane, warp);
    mma_gemm(g_Ws_hi + 2*65536, g_Ws_lo + 2*65536, sHb, sWb, CK, tid);
    frag_add_bias(CK, bk + 256, lane, warp);

    // ---- logits in registers: partner rows via shfl_xor(.,4) ----
    {
        float ls[2][2] = {{0.f,0.f},{0.f,0.f}};
        float lc[2][2] = {{0.f,0.f},{0.f,0.f}};
        #pragma unroll
        for (int mi = 0; mi < 2; mi++)
            #pragma unroll
            for (int ni = 0; ni < 4; ni++)
                #pragma unroll
                for (int hf = 0; hf < 2; hf++) {
                    float q0 = CQ[mi][ni][hf*2], q1 = CQ[mi][ni][hf*2+1];
                    float k0 = CK[mi][ni][hf*2], k1 = CK[mi][ni][hf*2+1];
                    float k0p = __shfl_xor_sync(0xffffffffu, k0, 4);
                    float k1p = __shfl_xor_sync(0xffffffffu, k1, 4);
                    ls[mi][hf] = fmaf(q0, k0, fmaf(q1, k1, ls[mi][hf]));
                    lc[mi][hf] = fmaf(q0, k0p, fmaf(q1, k1p, lc[mi][hf]));
                }
        #pragma unroll
        for (int mi = 0; mi < 2; mi++)
            #pragma unroll
            for (int hf = 0; hf < 2; hf++) {
                float a = ls[mi][hf], b = lc[mi][hf];
                a += __shfl_xor_sync(0xffffffffu, a, 1);
                a += __shfl_xor_sync(0xffffffffu, a, 2);
                b += __shfl_xor_sync(0xffffffffu, b, 1);
                b += __shfl_xor_sync(0xffffffffu, b, 2);
                if ((lane & 3) == 0) {
                    int row = mi*16 + hf*8 + (lane >> 2);
                    int head = warp >> 1;
                    atomicAdd(&s_part[row][head][0], a);
                    atomicAdd(&s_part[row][head][1], b);
                }
            }
    }
    __syncthreads();

    // ---- softmax: 128 items (row, head) ----
    if (tid < MTOK*4) {
        int row = tid >> 2, h = tid & 3;
        int p = row >> 1, s = row & 1;
        float lss = s_part[row][h][0] * 0.125f;
        float lcr = s_part[row][h][1] * 0.125f;
        float l0 = s ? lcr : lss;
        float l1 = s ? lss : lcr;
        float mx = fmaxf(l0, l1);
        float e0 = expf(l0 - mx), e1 = expf(l1 - mx);
        float inv = 1.f / (e0 + e1);
        s_attn[p][h][s][0] = e0 * inv;
        s_attn[p][h][s][1] = e1 * inv;
    }
    __syncthreads();

    // ---- U = h @ (Wv@WoW1) -> registers; attn-combine; h = h2 + comb + bvwbo
    {
        float CU[2][4][4];
        mma_gemm(g_Ws_hi + 3*65536, g_Ws_lo + 3*65536, sHb, sWb, CU, tid);
        int head = warp >> 1;
        #pragma unroll
        for (int mi = 0; mi < 2; mi++)
            #pragma unroll
            for (int hf = 0; hf < 2; hf++) {
                int row = mi*16 + hf*8 + (lane >> 2);
                int p = row >> 1, s = row & 1;
                float a0 = s_attn[p][head][s][0], a1 = s_attn[p][head][s][1];
                #pragma unroll
                for (int ni = 0; ni < 4; ni++) {
                    float v0v = CU[mi][ni][hf*2], v1v = CU[mi][ni][hf*2+1];
                    float v0p = __shfl_xor_sync(0xffffffffu, v0v, 4);
                    float v1p = __shfl_xor_sync(0xffffffffu, v1v, 4);
                    float ve0 = s ? v0p : v0v;
                    float vo0 = s ? v0v : v0p;
                    float ve1 = s ? v1p : v1v;
                    float vo1 = s ? v1v : v1p;
                    int col = warp*32 + ni*8 + (lane & 3)*2;
                    float add0 = a0*ve0 + a1*vo0 + __ldg(g_bvwbo + col);
                    float add1 = a0*ve1 + a1*vo1 + __ldg(g_bvwbo + col + 1);
                    float h0v = rec(Hh, Hl, row*RS + col)     + add0;
                    float h1v = rec(Hh, Hl, row*RS + col + 1) + add1;
                    sst(Hh + row*RS + col,     Hl + row*RS + col,     h0v);
                    sst(Hh + row*RS + col + 1, Hl + row*RS + col + 1, h1v);
                }
            }
    }
    __syncthreads();
    lnorm(Hh, Hl, ln1_s + 256, ln1_b + 256, tid);
    __syncthreads();

    // ---- h = LN2_1( h + tanh(h @ W2_1 + b2_1) ) ----
    {
        float C[2][4][4];
        mma_gemm(g_Ws_hi + 5*65536, g_Ws_lo + 5*65536, sHb, sWb, C, tid);
        #pragma unroll
        for (int ni = 0; ni < 4; ni++) {
            int col = warp*32 + ni*8 + (lane & 3)*2;
            float v0 = __ldg(b2 + 256 + col), v1 = __ldg(b2 + 256 + col + 1);
            #pragma unroll
            for (int mi = 0; mi < 2; mi++)
                #pragma unroll
                for (int hf = 0; hf < 2; hf++) {
                    int row = mi*16 + (lane >> 2) + hf*8;
                    float h0v = rec(Hh, Hl, row*RS + col)     + tanhf(C[mi][ni][hf*2]   + v0);
                    float h1v = rec(Hh, Hl, row*RS + col + 1) + tanhf(C[mi][ni][hf*2+1] + v1);
                    sst(Hh + row*RS + col,     Hl + row*RS + col,     h0v);
                    sst(Hh + row*RS + col + 1, Hl + row*RS + col + 1, h1v);
                }
        }
    }
    __syncthreads();
    lnorm(Hh, Hl, ln2_s + 256, ln2_b + 256, tid);
    __syncthreads();

    // ---- orbital projections: 8 warps = 8 combos, all pairs ----
    {
        int combo = warp;
        const float* Ws = (combo >= 4) ? Worb_i : Worb_r;
        int s = (combo >> 1) & 1, c = combo & 1;
        #pragma unroll 1
        for (int p = 0; p < PPB; p++) {
            float sum = 0.f;
            int hb = (p*2+s)*RS;
            #pragma unroll
            for (int k = 0; k < 8; k++) {
                int d = lane + 32*k;
                sum = fmaf(rec(Hh, Hl, hb + d), __ldg(Ws + d*2 + c), sum);
            }
            #pragma unroll
            for (int off = 16; off; off >>= 1) sum += __shfl_xor_sync(0xffffffffu, sum, off);
            if (lane == 0) s_orb[p][combo] = sum;
        }
    }
    __syncthreads();

    if (tid < PPB) {
        int p = tid;
        float th0 = s_tp[p][0][0], ph0 = s_tp[p][0][1];
        float th1 = s_tp[p][1][0], ph1 = s_tp[p][1][1];
        float c0, s0, c1, s1;
        sincosf(0.5f*th0, &s0, &c0);
        sincosf(0.5f*th1, &s1, &c1);
        float hd = 0.5f*(ph0 - ph1);
        float chd, shd; sincosf(hd, &shd, &chd);
        float re = (c0*s1 - c1*s0) * chd;
        float im = (c0*s1 + c1*s0) * shd;
        float chord2 = re*re + im*im;
        float trunc = 1.f - expf(-100.f * chord2);
        float t2 = trunc * trunc;
        float a_r = s_orb[p][0], b_r = s_orb[p][1], c_r = s_orb[p][2], d_r = s_orb[p][3];
        float a_i = s_orb[p][4], b_i = s_orb[p][5], c_i = s_orb[p][6], d_i = s_orb[p][7];
        float det_r = (a_r*d_r - a_i*d_i) - (b_r*c_r - b_i*c_i);
        float det_i = (a_r*d_i + a_i*d_r) - (b_r*c_i + b_i*c_r);
        det_r *= t2; det_i *= t2;
        int i = s_ij[p][0], j = s_ij[p][1];
        g_A[i*NE + j] = make_float2(det_r, det_i);
        g_A[j*NE + i] = make_float2(-det_r, -det_i);
    }
}

// ---------------- cusp matrix + bosonic log sum ---------------------------
__global__ void cusp_bos_kernel(const float* __restrict__ electrons)
{
    int i = blockIdx.x, j = threadIdx.x;
    __shared__ double s_red[2][8];
    float thi = electrons[2*i], phi_ = electrons[2*i+1];
    float thj = electrons[2*j], phj  = electrons[2*j+1];
    float ci, si, cj, sj;
    sincosf(0.5f*thi, &si, &ci);
    sincosf(0.5f*thj, &sj, &cj);
    float hd = 0.5f*(phi_ - phj);
    float chd, shd; sincosf(hd, &shd, &chd);
    float er = (ci*sj - si*cj) * chd;
    float ei = (ci*sj + si*cj) * shd;

    float eye = (i == j) ? 1.f : 0.f;
    float cr = er + eye, cim = ei;
    float rc2 = cr*cr + cim*cim;
    float g = expf(-100.f * rc2);
    float2 a = (i == j) ? make_float2(0.f, 0.f) : g_A[i*NE + j];
    a.x += cr * g;
    a.y += cim * g;
    g_A[i*NE + j] = a;

    double lr = 0.0, li = 0.0;
    if (i != j) {
        float rho2 = er*er + ei*ei;
        lr = 0.5 * log((double)(0.01f + rho2));
        li = (double)atan2f(ei, er);
    }
    int lane = j & 31, wrp = j >> 5;
    #pragma unroll
    for (int off = 16; off; off >>= 1) {
        lr += __shfl_xor_sync(0xffffffffu, lr, off);
        li += __shfl_xor_sync(0xffffffffu, li, off);
    }
    if (lane == 0) { s_red[0][wrp] = lr; s_red[1][wrp] = li; }
    __syncthreads();
    if (j == 0) {
        double a0 = 0.0, a1 = 0.0;
        #pragma unroll
        for (int w = 0; w < 8; w++) { a0 += s_red[0][w]; a1 += s_red[1][w]; }
        atomicAdd(&g_acc[0], a0);
        atomicAdd(&g_acc[1], a1);
    }
}

// ---------------- complex LU with partial pivoting (slogdet) --------------
__device__ __forceinline__ float2 cmul(float2 a, float2 b) {
    return make_float2(a.x*b.x - a.y*b.y, a.x*b.y + a.y*b.x);
}

__global__ void __launch_bounds__(1024) lu_kernel()
{
    __shared__ float2 s_prow[256];
    __shared__ float2 s_l[256];
    __shared__ float  s_mx[8];
    __shared__ int    s_mi[8];
    __shared__ float2 s_inv;
    __shared__ int    s_piv;
    int tid = threadIdx.x;
    double logabs = 0.0, argsum = 0.0;
    int par = 0;

    for (int k = 0; k < 256; k++) {
        if (tid < 256) {
            float v = -1.f; int idx = tid;
            if (tid >= k) { float2 a = g_A[tid*256 + k]; v = fabsf(a.x) + fabsf(a.y); }
            #pragma unroll
            for (int off = 16; off; off >>= 1) {
                float ov = __shfl_xor_sync(0xffffffffu, v, off);
                int   oi = __shfl_xor_sync(0xffffffffu, idx, off);
                if (ov > v) { v = ov; idx = oi; }
            }
            if ((tid & 31) == 0) { s_mx[tid>>5] = v; s_mi[tid>>5] = idx; }
        }
        __syncthreads();
        if (tid == 0) {
            float bv = -1.f; int bi = k;
            #pragma unroll
            for (int w = 0; w < 8; w++) if (s_mx[w] > bv) { bv = s_mx[w]; bi = s_mi[w]; }
            s_piv = bi;
        }
        __syncthreads();
        int pv = s_piv;
        if (pv != k && tid < 256) {
            float2 t = g_A[k*256 + tid];
            g_A[k*256 + tid] = g_A[pv*256 + tid];
            g_A[pv*256 + tid] = t;
        }
        __syncthreads();
        if (tid == 0) {
            if (pv != k) par ^= 1;
            float2 u = g_A[k*256 + k];
            double n2 = (double)u.x*u.x + (double)u.y*u.y;
            logabs += 0.5 * log(n2);
            argsum += atan2((double)u.y, (double)u.x);
            float d = u.x*u.x + u.y*u.y;
            s_inv = make_float2(u.x/d, -u.y/d);
        }
        __syncthreads();
        if (tid < 256) {
            s_prow[tid] = g_A[k*256 + tid];
            if (tid > k) {
                float2 l = cmul(g_A[tid*256 + k], s_inv);
                s_l[tid] = l;
                g_A[tid*256 + k] = l;
            }
        }
        __syncthreads();
        {
            int c = tid & 255, r0 = tid >> 8;
            if (c > k) {
                float2 pr = s_prow[c];
                #pragma unroll 4
                for (int i = k + 1 + r0; i < 256; i += 4) {
                    float2 l = s_l[i];
                    float2 a = g_A[i*256 + c];
                    a.x -= l.x*pr.x - l.y*pr.y;
                    a.y -= l.x*pr.y + l.y*pr.x;
                    g_A[i*256 + c] = a;
                }
            }
        }
        __syncthreads();
    }
    if (tid == 0) { g_lu_logabs = logabs; g_lu_arg = argsum; g_lu_par = par; }
}

// ---------------- init + finalize -----------------------------------------
__global__ void init_kernel() { g_acc[0] = 0.0; g_acc[1] = 0.0; }

__global__ void finalize_kernel(float* out)
{
    const double PI = 3.14159265358979323846;
    double logabs = g_lu_logabs;
    double arg = g_lu_arg + (g_lu_par ? PI : 0.0);
    double w = fmod(arg, 2.0*PI);
    if (w >  PI) w -= 2.0*PI;
    if (w <= -PI) w += 2.0*PI;
    out[0] = (float)(0.5*logabs + g_acc[0]);
    out[1] = (float)(0.5*w      + g_acc[1]);
}

// ---------------- launch ---------------------------------------------------
extern "C" void kernel_launch(void* const* d_in, const int* in_sizes, int n_in,
                              void* d_out, int out_size)
{
    const float* electrons = (const float*)d_in[0];
    const float* W_in   = (const float*)d_in[1];
    const float* Wq     = (const float*)d_in[2];
    const float* bq     = (const float*)d_in[3];
    const float* Wk     = (const float*)d_in[4];
    const float* bk     = (const float*)d_in[5];
    const float* Wv     = (const float*)d_in[6];
    const float* bv     = (const float*)d_in[7];
    const float* Wo     = (const float*)d_in[8];
    const float* bo     = (const float*)d_in[9];
    const float* W1     = (const float*)d_in[10];
    const float* ln1_s  = (const float*)d_in[11];
    const float* ln1_b  = (const float*)d_in[12];
    const float* W2     = (const float*)d_in[13];
    const float* b2     = (const float*)d_in[14];
    const float* ln2_s  = (const float*)d_in[15];
    const float* ln2_b  = (const float*)d_in[16];
    const float* Worb_r = (const float*)d_in[17];
    const float* Worb_i = (const float*)d_in[18];

    cudaFuncSetAttribute(pair_kernel, cudaFuncAttributeMaxDynamicSharedMemorySize, SMEM_BYTES);

    wow1_kernel<<<2*257, 256>>>(Wo, W1, bo);
    wvw_kernel<<<257, 256>>>(Wv, bv);
    prep_kernel<<<256, 256>>>(electrons, W_in, Wq, bq, Wk, bk, Wv, bv);
    gram_z_kernel<<<256, 256>>>();
    pbasis_kernel<<<1281, 256>>>(W2, ln1_s, ln1_b);
    convert_host<<<3*256, 256>>>(Wq, Wk, W2);
    init_kernel<<<1, 1>>>();
    pair_kernel<<<NBLOCKS, NTHREADS, SMEM_BYTES>>>(electrons, bq, bk,
                                                   ln1_s, ln1_b, b2, ln2_s, ln2_b,
                                                   Worb_r, Worb_i);
    cusp_bos_kernel<<<NE, NE>>>(electrons);
    lu_kernel<<<1, 1024>>>();
    finalize_kernel<<<1, 1>>>((float*)d_out);
}

// round 17
// speedup vs baseline: 1.0779x; 1.0295x over previous
#include <cuda_runtime.h>
#include <cuda_bf16.h>
#include <math.h>
#include <cstdint>

#define NE  256
#define P_TOTAL 32640
#define PPB 16
#define MTOK 32                        /* 2*PPB tokens per CTA */
#define NBLOCKS (P_TOTAL/PPB)          /* 2040 */
#define NTHREADS 256
#define RS  264                        /* padded row stride, bf16 elems */
#define RSB (RS*2)                     /* 528 bytes */
#define PL  (MTOK*RS)                  /* one activation plane, halves */
#define PLB (PL*2)                     /* plane bytes (16896) */
#define WCHB (64*RS*2)                 /* W chunk hi+lo rows: 33792 bytes */
#define SMEM_BYTES (2*PLB + 2*WCHB)    /* 33792 + 67584 = 101376 -> 2 CTAs/SM */

// ---------------- device globals (no allocations) --------------------------
// split-bf16 weights: slots 1=Wq_1, 2=Wk_1, 3=Wvw (Wv_1@WoW1_1), 5=W2_1
__device__ __nv_bfloat16 g_Ws_hi[6*65536];
__device__ __nv_bfloat16 g_Ws_lo[6*65536];
__device__ __align__(16) float g_h0[65536];
__device__ __align__(16) float g_q0[65536], g_k0[65536], g_v0[65536];
__device__ __align__(16) float g_k0t[65536];   // transposed: [d][e]
__device__ __align__(16) float g_G[4*65536];
__device__ __align__(16) float g_Z[65536*4];
__device__ __align__(16) float g_WoW1[2*65536];
__device__ __align__(16) float g_boW1[2*256];
__device__ __align__(16) float g_bvwbo[256];   // bv_1@WoW1_1 + bo_1@W1_1
__device__ __align__(16) float g_Ph0[65536];
__device__ __align__(16) float g_PZ[65536*4];
__device__ __align__(16) float g_c1[256], g_c2[256], g_c3[256];
__device__ float2 g_A[NE*NE];
__device__ double g_acc[2];
__device__ double g_lu_logabs, g_lu_arg;
__device__ int    g_lu_par;

// ---------------- helpers ---------------------------------------------------
__device__ __forceinline__ uint32_t smem_u32(const void* p) {
    return (uint32_t)__cvta_generic_to_shared(p);
}
__device__ __forceinline__ void sst(__nv_bfloat16* h, __nv_bfloat16* l, float x) {
    __nv_bfloat16 hi = __float2bfloat16_rn(x);
    *h = hi;
    *l = __float2bfloat16_rn(x - __bfloat162float(hi));
}
__device__ __forceinline__ float rec(const __nv_bfloat16* h, const __nv_bfloat16* l, int idx) {
    return __bfloat162float(h[idx]) + __bfloat162float(l[idx]);
}

// ---------------- precompute kernels ---------------------------------------
__global__ void wow1_kernel(const float* __restrict__ Wo, const float* __restrict__ W1,
                            const float* __restrict__ bo)
{
    int b = blockIdx.x, col = threadIdx.x;
    int l = b / 257, r = b % 257;
    const float* W1l = W1 + l*65536;
    float acc = 0.f;
    if (r < 256) {
        const float* Wol = Wo + l*65536 + r*256;
        for (int d = 0; d < 256; d++) acc = fmaf(Wol[d], W1l[d*256 + col], acc);
        g_WoW1[l*65536 + r*256 + col] = acc;
    } else {
        const float* bol = bo + l*256;
        for (int d = 0; d < 256; d++) acc = fmaf(bol[d], W1l[d*256 + col], acc);
        g_boW1[l*256 + col] = acc;
    }
}

// slot 3 = split(Wv_1 @ WoW1_1); g_bvwbo = bv_1 @ WoW1_1 + boW1_1
__global__ void wvw_kernel(const float* __restrict__ Wv, const float* __restrict__ bv)
{
    __shared__ float src[256];
    int b = blockIdx.x, col = threadIdx.x;
    const float* W = g_WoW1 + 65536;
    if (b < 256) {
        src[col] = __ldg(Wv + 65536 + b*256 + col);
        __syncthreads();
        float acc = 0.f;
        for (int m = 0; m < 256; m++) acc = fmaf(src[m], __ldg(W + m*256 + col), acc);
        __nv_bfloat16 hi = __float2bfloat16_rn(acc);
        g_Ws_hi[3*65536 + b*256 + col] = hi;
        g_Ws_lo[3*65536 + b*256 + col] = __float2bfloat16_rn(acc - __bfloat162float(hi));
    } else {
        src[col] = __ldg(bv + 256 + col);
        __syncthreads();
        float acc = 0.f;
        for (int m = 0; m < 256; m++) acc = fmaf(src[m], __ldg(W + m*256 + col), acc);
        g_bvwbo[col] = acc + g_boW1[256 + col];
    }
}

__global__ void prep_kernel(const float* __restrict__ electrons, const float* __restrict__ W_in,
                            const float* __restrict__ Wq, const float* __restrict__ bq,
                            const float* __restrict__ Wk, const float* __restrict__ bk,
                            const float* __restrict__ Wv, const float* __restrict__ bv)
{
    __shared__ float hrow[256];
    int e = blockIdx.x, col = threadIdx.x;
    float th = electrons[2*e], ph = electrons[2*e+1];
    float st, ct, sp, cp;
    sincosf(th, &st, &ct);
    sincosf(ph, &sp, &cp);
    float f0 = ct, f1 = st*cp, f2 = st*sp;
    float h = f0*__ldg(W_in + col) + f1*__ldg(W_in + 256 + col) + f2*__ldg(W_in + 512 + col);
    g_h0[e*256 + col] = h;
    hrow[col] = h;
    __syncthreads();
    float q = __ldg(bq + col), k = __ldg(bk + col), v = __ldg(bv + col);
    for (int d = 0; d < 256; d++) {
        float hv = hrow[d];
        q = fmaf(hv, __ldg(Wq + d*256 + col), q);
        k = fmaf(hv, __ldg(Wk + d*256 + col), k);
        v = fmaf(hv, __ldg(Wv + d*256 + col), v);
    }
    g_q0[e*256 + col] = q;
    g_k0[e*256 + col] = k;
    g_k0t[col*256 + e] = k;
    g_v0[e*256 + col] = v;
}

__global__ void gram_z_kernel()
{
    __shared__ float qrow[256], vrow[256];
    int i = blockIdx.x, t = threadIdx.x;
    qrow[t] = g_q0[i*256 + t];
    vrow[t] = g_v0[i*256 + t];
    __syncthreads();
    #pragma unroll
    for (int h = 0; h < 4; h++) {
        float acc = 0.f;
        #pragma unroll 8
        for (int d = 0; d < 64; d++)
            acc = fmaf(qrow[h*64 + d], __ldg(g_k0t + (h*64 + d)*256 + t), acc);
        g_G[h*65536 + i*256 + t] = acc * 0.125f;
    }
    #pragma unroll
    for (int h = 0; h < 4; h++) {
        float acc = 0.f;
        #pragma unroll 8
        for (int d = 0; d < 64; d++)
            acc = fmaf(vrow[h*64 + d], __ldg(g_WoW1 + (h*64 + d)*256 + t), acc);
        g_Z[i*1024 + h*256 + t] = acc;
    }
}

__global__ void pbasis_kernel(const float* __restrict__ W2, const float* __restrict__ ln1_s,
                              const float* __restrict__ ln1_b)
{
    __shared__ float src[256];
    int b = blockIdx.x, col = threadIdx.x;
    if (b < 256) {
        src[col] = g_h0[b*256 + col] * __ldg(ln1_s + col);
        __syncthreads();
        float acc = 0.f;
        for (int d = 0; d < 256; d++) acc = fmaf(src[d], __ldg(W2 + d*256 + col), acc);
        g_Ph0[b*256 + col] = acc;
    } else if (b < 1280) {
        int idx = b - 256;
        src[col] = g_Z[idx*256 + col] * __ldg(ln1_s + col);
        __syncthreads();
        float acc = 0.f;
        for (int d = 0; d < 256; d++) acc = fmaf(src[d], __ldg(W2 + d*256 + col), acc);
        g_PZ[idx*256 + col] = acc;
    } else {
        src[col] = g_boW1[col] * __ldg(ln1_s + col);
        __syncthreads();
        float a1 = 0.f, a2 = 0.f, a3 = 0.f;
        for (int d = 0; d < 256; d++) {
            float w = __ldg(W2 + d*256 + col);
            a1 = fmaf(src[d], w, a1);
            a2 = fmaf(__ldg(ln1_s + d), w, a2);
            a3 = fmaf(__ldg(ln1_b + d), w, a3);
        }
        g_c1[col] = a1; g_c2[col] = a2; g_c3[col] = a3;
    }
}

// split host weights: m 0..2 -> {Wq_1->1, Wk_1->2, W2_1->5}
__global__ void convert_host(const float* __restrict__ Wq, const float* __restrict__ Wk,
                             const float* __restrict__ W2)
{
    int idx = blockIdx.x * 256 + threadIdx.x;
    int m = idx >> 16, off = idx & 65535;
    const float* src; int slot;
    switch (m) {
        case 0: src = Wq + 65536;  slot = 1; break;
        case 1: src = Wk + 65536;  slot = 2; break;
        default: src = W2 + 65536; slot = 5; break;
    }
    float v = src[off];
    __nv_bfloat16 hi = __float2bfloat16_rn(v);
    g_Ws_hi[slot*65536 + off] = hi;
    g_Ws_lo[slot*65536 + off] = __float2bfloat16_rn(v - __bfloat162float(hi));
}

// ---------------- split-bf16 GEMM: 32-row chunks, DOUBLE buffered -----------
__device__ __forceinline__ void cp_load_chunk(const __nv_bfloat16* __restrict__ gWhi,
                                              const __nv_bfloat16* __restrict__ gWlo,
                                              int chunk, uint32_t sWbuf, int tid)
{
    #pragma unroll
    for (int i = 0; i < 8; i++) {
        int g = tid + i*NTHREADS;             // 2048 granules of 16B
        int plane = g >> 10;
        int row = (g >> 5) & 31, c16 = g & 31;
        uint32_t s = sWbuf + (plane*32 + row)*RSB + c16*16;
        const __nv_bfloat16* base = plane ? gWlo : gWhi;
        const void* gp = base + (chunk*32 + row)*256 + c16*8;
        asm volatile("cp.async.cg.shared.global [%0],[%1],16;\n" :: "r"(s), "l"(gp));
    }
    asm volatile("cp.async.commit_group;\n");
}

// double-buffered: load(c+1) issued AFTER the barrier (prev compute provably
// done with that buffer); one barrier per chunk + one trailing barrier.
__device__ __forceinline__ void mma_gemm(const __nv_bfloat16* __restrict__ gWhi,
                                         const __nv_bfloat16* __restrict__ gWlo,
                                         uint32_t sA, uint32_t sW,
                                         float C[2][4][4], int tid)
{
    int lane = tid & 31, warp = tid >> 5;
    #pragma unroll
    for (int a = 0; a < 2; a++)
        #pragma unroll
        for (int b = 0; b < 4; b++)
            #pragma unroll
            for (int d = 0; d < 4; d++) C[a][b][d] = 0.f;

    cp_load_chunk(gWhi, gWlo, 0, sW, tid);
    #pragma unroll 1
    for (int c = 0; c < 8; c++) {
        asm volatile("cp.async.wait_group 0;\n");
        __syncthreads();
        if (c < 7)
            cp_load_chunk(gWhi, gWlo, c+1, sW + ((c+1)&1)*WCHB, tid);
        uint32_t wb = sW + (c&1)*WCHB;
        #pragma unroll
        for (int ks = 0; ks < 2; ks++) {
            int k0 = c*32 + ks*16;
            uint32_t ahi[2][4], alo[2][4], bhi[2][4], blo[2][4];
            #pragma unroll
            for (int mi = 0; mi < 2; mi++) {
                uint32_t addr = sA + (mi*16 + (lane & 15))*RSB + (k0 + ((lane >> 4) << 3))*2;
                asm volatile("ldmatrix.sync.aligned.m8n8.x4.shared.b16 {%0,%1,%2,%3},[%4];\n"
                    : "=r"(ahi[mi][0]), "=r"(ahi[mi][1]), "=r"(ahi[mi][2]), "=r"(ahi[mi][3]) : "r"(addr));
                asm volatile("ldmatrix.sync.aligned.m8n8.x4.shared.b16 {%0,%1,%2,%3},[%4];\n"
                    : "=r"(alo[mi][0]), "=r"(alo[mi][1]), "=r"(alo[mi][2]), "=r"(alo[mi][3]) : "r"(addr + PLB));
            }
            #pragma unroll
            for (int nh = 0; nh < 2; nh++) {
                uint32_t addr = wb + (ks*16 + (lane & 15))*RSB
                              + (warp*32 + nh*16 + ((lane >> 4) << 3))*2;
                asm volatile("ldmatrix.sync.aligned.m8n8.x4.trans.shared.b16 {%0,%1,%2,%3},[%4];\n"
                    : "=r"(bhi[nh][0]), "=r"(bhi[nh][1]), "=r"(bhi[nh][2]), "=r"(bhi[nh][3]) : "r"(addr));
                asm volatile("ldmatrix.sync.aligned.m8n8.x4.trans.shared.b16 {%0,%1,%2,%3},[%4];\n"
                    : "=r"(blo[nh][0]), "=r"(blo[nh][1]), "=r"(blo[nh][2]), "=r"(blo[nh][3]) : "r"(addr + 32*RSB));
            }
            #pragma unroll
            for (int mi = 0; mi < 2; mi++)
                #pragma unroll
                for (int ni = 0; ni < 4; ni++) {
                    uint32_t bh0 = bhi[ni>>1][(ni&1)*2], bh1 = bhi[ni>>1][(ni&1)*2 + 1];
                    uint32_t bl0 = blo[ni>>1][(ni&1)*2], bl1 = blo[ni>>1][(ni&1)*2 + 1];
                    asm volatile("mma.sync.aligned.m16n8k16.row.col.f32.bf16.bf16.f32 "
                        "{%0,%1,%2,%3},{%4,%5,%6,%7},{%8,%9},{%0,%1,%2,%3};\n"
                        : "+f"(C[mi][ni][0]), "+f"(C[mi][ni][1]),
                          "+f"(C[mi][ni][2]), "+f"(C[mi][ni][3])
                        : "r"(ahi[mi][0]), "r"(ahi[mi][1]), "r"(ahi[mi][2]), "r"(ahi[mi][3]),
                          "r"(bh0), "r"(bh1));
                    asm volatile("mma.sync.aligned.m16n8k16.row.col.f32.bf16.bf16.f32 "
                        "{%0,%1,%2,%3},{%4,%5,%6,%7},{%8,%9},{%0,%1,%2,%3};\n"
                        : "+f"(C[mi][ni][0]), "+f"(C[mi][ni][1]),
                          "+f"(C[mi][ni][2]), "+f"(C[mi][ni][3])
                        : "r"(alo[mi][0]), "r"(alo[mi][1]), "r"(alo[mi][2]), "r"(alo[mi][3]),
                          "r"(bh0), "r"(bh1));
                    asm volatile("mma.sync.aligned.m16n8k16.row.col.f32.bf16.bf16.f32 "
                        "{%0,%1,%2,%3},{%4,%5,%6,%7},{%8,%9},{%0,%1,%2,%3};\n"
                        : "+f"(C[mi][ni][0]), "+f"(C[mi][ni][1]),
                          "+f"(C[mi][ni][2]), "+f"(C[mi][ni][3])
                        : "r"(ahi[mi][0]), "r"(ahi[mi][1]), "r"(ahi[mi][2]), "r"(ahi[mi][3]),
                          "r"(bl0), "r"(bl1));
                }
        }
    }
    __syncthreads();
}

__device__ __forceinline__ void frag_add_bias(float C[2][4][4], const float* __restrict__ b,
                                              int lane, int warp)
{
    #pragma unroll
    for (int ni = 0; ni < 4; ni++) {
        int col = warp*32 + ni*8 + (lane & 3)*2;
        float v0 = __ldg(b + col), v1 = __ldg(b + col + 1);
        #pragma unroll
        for (int mi = 0; mi < 2; mi++)
            #pragma unroll
            for (int hf = 0; hf < 2; hf++) {
                C[mi][ni][hf*2]   += v0;
                C[mi][ni][hf*2+1] += v1;
            }
    }
}

__device__ __forceinline__ void lnorm(__nv_bfloat16* Hh, __nv_bfloat16* Hl,
                                      const float* __restrict__ sc,
                                      const float* __restrict__ bi, int tid)
{
    int lane = tid & 31, warp = tid >> 5;
    #pragma unroll 1
    for (int rr = 0; rr < 4; rr++) {
        int row = warp*4 + rr;
        float xs[8];
        float s1 = 0.f, s2 = 0.f;
        #pragma unroll
        for (int i = 0; i < 8; i++) {
            int col = lane*8 + i;
            float f = rec(Hh, Hl, row*RS + col);
            xs[i] = f;
            s1 += f; s2 += f*f;
        }
        #pragma unroll
        for (int off = 16; off; off >>= 1) {
            s1 += __shfl_xor_sync(0xffffffffu, s1, off);
            s2 += __shfl_xor_sync(0xffffffffu, s2, off);
        }
        float m   = s1 * (1.f/256.f);
        float var = s2 * (1.f/256.f) - m*m;
        float inv = rsqrtf(var + 1e-5f);
        #pragma unroll
        for (int i = 0; i < 8; i++) {
            int col = lane*8 + i;
            float y = (xs[i] - m)*inv*__ldg(sc+col) + __ldg(bi+col);
            sst(Hh + row*RS + col, Hl + row*RS + col, y);
        }
    }
}

// ---------------- pair transformer ------------------------------------------
__global__ void __launch_bounds__(NTHREADS, 2) pair_kernel(
    const float* __restrict__ electrons,
    const float* __restrict__ bq, const float* __restrict__ bk,
    const float* __restrict__ ln1_s, const float* __restrict__ ln1_b,
    const float* __restrict__ b2,
    const float* __restrict__ ln2_s, const float* __restrict__ ln2_b,
    const float* __restrict__ Worb_r, const float* __restrict__ Worb_i)
{
    extern __shared__ __nv_bfloat16 smem[];
    __nv_bfloat16* Hh = smem;
    __nv_bfloat16* Hl = Hh + PL;
    uint32_t sHb = smem_u32(Hh);
    uint32_t sWb = smem_u32(Hl + PL);

    __shared__ float s_tp[PPB][2][2];
    __shared__ int   s_ij[PPB][2];
    __shared__ float s_part[MTOK][4][2];
    __shared__ float s_attn[PPB][4][2][2];
    __shared__ float s_orb[PPB][8];

    int tid = threadIdx.x;
    int lane = tid & 31, warp = tid >> 5;

    // ---- pair index decode ----
    if (tid < PPB) {
        long long p = (long long)blockIdx.x * PPB + tid;
        double pd = (double)p;
        int i = (int)floor((2.0*NE - 1.0 - sqrt((2.0*NE-1.0)*(2.0*NE-1.0) - 8.0*pd)) * 0.5);
        if (i < 0) i = 0;
        if (i > NE-2) i = NE-2;
        while (i > 0 && (long long)i*(2*NE-1-i)/2 > p) i--;
        while ((long long)(i+1)*(2*NE-1-(i+1))/2 <= p) i++;
        long long base = (long long)i*(2*NE-1-i)/2;
        int j = (int)(p - base) + i + 1;
        s_ij[tid][0] = i; s_ij[tid][1] = j;
    }
    __syncthreads();
    if (tid < PPB*2) {
        int p = tid >> 1, s = tid & 1;
        int e = s_ij[p][s];
        s_tp[p][s][0] = electrons[2*e];
        s_tp[p][s][1] = electrons[2*e+1];
    }
    {
        float* sp = &s_part[0][0][0];
        if (tid < MTOK*4*2) sp[tid] = 0.f;
    }
    __syncthreads();

    // ---- layer 0 fully analytic -> H planes (8 warps x 2 pairs) ----
    #pragma unroll 1
    for (int pq = 0; pq < 2; pq++) {
        int pr = warp*2 + pq;
        int ei = s_ij[pr][0], ej = s_ij[pr][1];
        float a0s[2][4], a1s[2][4];
        #pragma unroll
        for (int s = 0; s < 2; s++) {
            int self = s ? ej : ei;
            #pragma unroll
            for (int h = 0; h < 4; h++) {
                float l0 = __ldg(g_G + h*65536 + self*256 + ei);
                float l1 = __ldg(g_G + h*65536 + self*256 + ej);
                float mx = fmaxf(l0, l1);
                float e0 = expf(l0 - mx), e1 = expf(l1 - mx);
                float inv = 1.f / (e0 + e1);
                a0s[s][h] = e0 * inv;
                a1s[s][h] = e1 * inv;
            }
        }
        int col0 = lane*8;
        float acc0[8], acc1[8], ap0[8], ap1[8];
        {
            float4 bw0 = __ldg((const float4*)(g_boW1 + col0));
            float4 bw1 = __ldg((const float4*)(g_boW1 + col0 + 4));
            float4 hi0 = __ldg((const float4*)(g_h0 + ei*256 + col0));
            float4 hi1 = __ldg((const float4*)(g_h0 + ei*256 + col0 + 4));
            float4 hj0 = __ldg((const float4*)(g_h0 + ej*256 + col0));
            float4 hj1 = __ldg((const float4*)(g_h0 + ej*256 + col0 + 4));
            acc0[0]=hi0.x+bw0.x; acc0[1]=hi0.y+bw0.y; acc0[2]=hi0.z+bw0.z; acc0[3]=hi0.w+bw0.w;
            acc0[4]=hi1.x+bw1.x; acc0[5]=hi1.y+bw1.y; acc0[6]=hi1.z+bw1.z; acc0[7]=hi1.w+bw1.w;
            acc1[0]=hj0.x+bw0.x; acc1[1]=hj0.y+bw0.y; acc1[2]=hj0.z+bw0.z; acc1[3]=hj0.w+bw0.w;
            acc1[4]=hj1.x+bw1.x; acc1[5]=hj1.y+bw1.y; acc1[6]=hj1.z+bw1.z; acc1[7]=hj1.w+bw1.w;
            float4 c10 = __ldg((const float4*)(g_c1 + col0));
            float4 c11 = __ldg((const float4*)(g_c1 + col0 + 4));
            float4 pi0 = __ldg((const float4*)(g_Ph0 + ei*256 + col0));
            float4 pi1 = __ldg((const float4*)(g_Ph0 + ei*256 + col0 + 4));
            float4 pj0 = __ldg((const float4*)(g_Ph0 + ej*256 + col0));
            float4 pj1 = __ldg((const float4*)(g_Ph0 + ej*256 + col0 + 4));
            ap0[0]=pi0.x+c10.x; ap0[1]=pi0.y+c10.y; ap0[2]=pi0.z+c10.z; ap0[3]=pi0.w+c10.w;
            ap0[4]=pi1.x+c11.x; ap0[5]=pi1.y+c11.y; ap0[6]=pi1.z+c11.z; ap0[7]=pi1.w+c11.w;
            ap1[0]=pj0.x+c10.x; ap1[1]=pj0.y+c10.y; ap1[2]=pj0.z+c10.z; ap1[3]=pj0.w+c10.w;
            ap1[4]=pj1.x+c11.x; ap1[5]=pj1.y+c11.y; ap1[6]=pj1.z+c11.z; ap1[7]=pj1.w+c11.w;
        }
        #pragma unroll
        for (int h = 0; h < 4; h++) {
            float4 zi0 = __ldg((const float4*)(g_Z + ei*1024 + h*256 + col0));
            float4 zi1 = __ldg((const float4*)(g_Z + ei*1024 + h*256 + col0 + 4));
            float4 zj0 = __ldg((const float4*)(g_Z + ej*1024 + h*256 + col0));
            float4 zj1 = __ldg((const float4*)(g_Z + ej*1024 + h*256 + col0 + 4));
            float4 qi0 = __ldg((const float4*)(g_PZ + ei*1024 + h*256 + col0));
            float4 qi1 = __ldg((const float4*)(g_PZ + ei*1024 + h*256 + col0 + 4));
            float4 qj0 = __ldg((const float4*)(g_PZ + ej*1024 + h*256 + col0));
            float4 qj1 = __ldg((const float4*)(g_PZ + ej*1024 + h*256 + col0 + 4));
            float zi[8] = {zi0.x, zi0.y, zi0.z, zi0.w, zi1.x, zi1.y, zi1.z, zi1.w};
            float zj[8] = {zj0.x, zj0.y, zj0.z, zj0.w, zj1.x, zj1.y, zj1.z, zj1.w};
            float qi[8] = {qi0.x, qi0.y, qi0.z, qi0.w, qi1.x, qi1.y, qi1.z, qi1.w};
            float qj[8] = {qj0.x, qj0.y, qj0.z, qj0.w, qj1.x, qj1.y, qj1.z, qj1.w};
            #pragma unroll
            for (int i = 0; i < 8; i++) {
                acc0[i] = fmaf(a0s[0][h], zi[i], fmaf(a1s[0][h], zj[i], acc0[i]));
                acc1[i] = fmaf(a0s[1][h], zi[i], fmaf(a1s[1][h], zj[i], acc1[i]));
                ap0[i]  = fmaf(a0s[0][h], qi[i], fmaf(a1s[0][h], qj[i], ap0[i]));
                ap1[i]  = fmaf(a0s[1][h], qi[i], fmaf(a1s[1][h], qj[i], ap1[i]));
            }
        }
        #define TOKEN_FINISH(ACC, AP, ROW)                                           \
        do {                                                                         \
            float s1 = 0.f, s2 = 0.f;                                                \
            _Pragma("unroll")                                                        \
            for (int i = 0; i < 8; i++) { s1 += ACC[i]; s2 += ACC[i]*ACC[i]; }       \
            _Pragma("unroll")                                                        \
            for (int off = 16; off; off >>= 1) {                                     \
                s1 += __shfl_xor_sync(0xffffffffu, s1, off);                         \
                s2 += __shfl_xor_sync(0xffffffffu, s2, off);                         \
            }                                                                        \
            float m   = s1 * (1.f/256.f);                                            \
            float var = s2 * (1.f/256.f) - m*m;                                      \
            float inv1 = rsqrtf(var + 1e-5f);                                        \
            float h2v[8];                                                            \
            float t1 = 0.f, t2s = 0.f;                                               \
            _Pragma("unroll")                                                        \
            for (int i = 0; i < 8; i++) {                                            \
                int col = col0 + i;                                                  \
                float h1 = (ACC[i] - m)*inv1*__ldg(ln1_s + col) + __ldg(ln1_b + col);\
                float t2v = inv1*(AP[i] - m*__ldg(g_c2 + col)) + __ldg(g_c3 + col);  \
                float h2 = h1 + tanhf(t2v + __ldg(b2 + col));                        \
                h2v[i] = h2; t1 += h2; t2s += h2*h2;                                 \
            }                                                                        \
            _Pragma("unroll")                                                        \
            for (int off = 16; off; off >>= 1) {                                     \
                t1 += __shfl_xor_sync(0xffffffffu, t1, off);                         \
                t2s += __shfl_xor_sync(0xffffffffu, t2s, off);                       \
            }                                                                        \
            float m2   = t1 * (1.f/256.f);                                           \
            float var2 = t2s * (1.f/256.f) - m2*m2;                                  \
            float inv2 = rsqrtf(var2 + 1e-5f);                                       \
            _Pragma("unroll")                                                        \
            for (int i = 0; i < 8; i++) {                                            \
                int col = col0 + i;                                                  \
                float y = (h2v[i] - m2)*inv2*__ldg(ln2_s + col) + __ldg(ln2_b + col);\
                sst(Hh + (ROW)*RS + col, Hl + (ROW)*RS + col, y);                    \
            }                                                                        \
        } while (0)
        TOKEN_FINISH(acc0, ap0, pr*2);
        TOKEN_FINISH(acc1, ap1, pr*2 + 1);
        #undef TOKEN_FINISH
    }
    __syncthreads();

    // ---- layer 1 Q, K GEMMs -> registers ----
    float CQ[2][4][4], CK[2][4][4];
    mma_gemm(g_Ws_hi + 1*65536, g_Ws_lo + 1*65536, sHb, sWb, CQ, tid);
    frag_add_bias(CQ, bq + 256, lane, warp);
    mma_gemm(g_Ws_hi + 2*65536, g_Ws_lo + 2*65536, sHb, sWb, CK, tid);
    frag_add_bias(CK, bk + 256, lane, warp);

    // ---- logits in registers: partner rows via shfl_xor(.,4) ----
    {
        float ls[2][2] = {{0.f,0.f},{0.f,0.f}};
        float lc[2][2] = {{0.f,0.f},{0.f,0.f}};
        #pragma unroll
        for (int mi = 0; mi < 2; mi++)
            #pragma unroll
            for (int ni = 0; ni < 4; ni++)
                #pragma unroll
                for (int hf = 0; hf < 2; hf++) {
                    float q0 = CQ[mi][ni][hf*2], q1 = CQ[mi][ni][hf*2+1];
                    float k0 = CK[mi][ni][hf*2], k1 = CK[mi][ni][hf*2+1];
                    float k0p = __shfl_xor_sync(0xffffffffu, k0, 4);
                    float k1p = __shfl_xor_sync(0xffffffffu, k1, 4);
                    ls[mi][hf] = fmaf(q0, k0, fmaf(q1, k1, ls[mi][hf]));
                    lc[mi][hf] = fmaf(q0, k0p, fmaf(q1, k1p, lc[mi][hf]));
                }
        #pragma unroll
        for (int mi = 0; mi < 2; mi++)
            #pragma unroll
            for (int hf = 0; hf < 2; hf++) {
                float a = ls[mi][hf], b = lc[mi][hf];
                a += __shfl_xor_sync(0xffffffffu, a, 1);
                a += __shfl_xor_sync(0xffffffffu, a, 2);
                b += __shfl_xor_sync(0xffffffffu, b, 1);
                b += __shfl_xor_sync(0xffffffffu, b, 2);
                if ((lane & 3) == 0) {
                    int row = mi*16 + hf*8 + (lane >> 2);
                    int head = warp >> 1;
                    atomicAdd(&s_part[row][head][0], a);
                    atomicAdd(&s_part[row][head][1], b);
                }
            }
    }
    __syncthreads();

    // ---- softmax: 128 items (row, head) ----
    if (tid < MTOK*4) {
        int row = tid >> 2, h = tid & 3;
        int p = row >> 1, s = row & 1;
        float lss = s_part[row][h][0] * 0.125f;
        float lcr = s_part[row][h][1] * 0.125f;
        float l0 = s ? lcr : lss;
        float l1 = s ? lss : lcr;
        float mx = fmaxf(l0, l1);
        float e0 = expf(l0 - mx), e1 = expf(l1 - mx);
        float inv = 1.f / (e0 + e1);
        s_attn[p][h][s][0] = e0 * inv;
        s_attn[p][h][s][1] = e1 * inv;
    }
    __syncthreads();

    // ---- U = h @ (Wv@WoW1) -> registers; attn-combine; h = h2 + comb + bvwbo
    {
        float CU[2][4][4];
        mma_gemm(g_Ws_hi + 3*65536, g_Ws_lo + 3*65536, sHb, sWb, CU, tid);
        int head = warp >> 1;
        #pragma unroll
        for (int mi = 0; mi < 2; mi++)
            #pragma unroll
            for (int hf = 0; hf < 2; hf++) {
                int row = mi*16 + hf*8 + (lane >> 2);
                int p = row >> 1, s = row & 1;
                float a0 = s_attn[p][head][s][0], a1 = s_attn[p][head][s][1];
                #pragma unroll
                for (int ni = 0; ni < 4; ni++) {
                    float v0v = CU[mi][ni][hf*2], v1v = CU[mi][ni][hf*2+1];
                    float v0p = __shfl_xor_sync(0xffffffffu, v0v, 4);
                    float v1p = __shfl_xor_sync(0xffffffffu, v1v, 4);
                    float ve0 = s ? v0p : v0v;
                    float vo0 = s ? v0v : v0p;
                    float ve1 = s ? v1p : v1v;
                    float vo1 = s ? v1v : v1p;
                    int col = warp*32 + ni*8 + (lane & 3)*2;
                    float add0 = a0*ve0 + a1*vo0 + __ldg(g_bvwbo + col);
                    float add1 = a0*ve1 + a1*vo1 + __ldg(g_bvwbo + col + 1);
                    float h0v = rec(Hh, Hl, row*RS + col)     + add0;
                    float h1v = rec(Hh, Hl, row*RS + col + 1) + add1;
                    sst(Hh + row*RS + col,     Hl + row*RS + col,     h0v);
                    sst(Hh + row*RS + col + 1, Hl + row*RS + col + 1, h1v);
                }
            }
    }
    __syncthreads();
    lnorm(Hh, Hl, ln1_s + 256, ln1_b + 256, tid);
    __syncthreads();

    // ---- h = LN2_1( h + tanh(h @ W2_1 + b2_1) ) ----
    {
        float C[2][4][4];
        mma_gemm(g_Ws_hi + 5*65536, g_Ws_lo + 5*65536, sHb, sWb, C, tid);
        #pragma unroll
        for (int ni = 0; ni < 4; ni++) {
            int col = warp*32 + ni*8 + (lane & 3)*2;
            float v0 = __ldg(b2 + 256 + col), v1 = __ldg(b2 + 256 + col + 1);
            #pragma unroll
            for (int mi = 0; mi < 2; mi++)
                #pragma unroll
                for (int hf = 0; hf < 2; hf++) {
                    int row = mi*16 + (lane >> 2) + hf*8;
                    float h0v = rec(Hh, Hl, row*RS + col)     + tanhf(C[mi][ni][hf*2]   + v0);
                    float h1v = rec(Hh, Hl, row*RS + col + 1) + tanhf(C[mi][ni][hf*2+1] + v1);
                    sst(Hh + row*RS + col,     Hl + row*RS + col,     h0v);
                    sst(Hh + row*RS + col + 1, Hl + row*RS + col + 1, h1v);
                }
        }
    }
    __syncthreads();
    lnorm(Hh, Hl, ln2_s + 256, ln2_b + 256, tid);
    __syncthreads();

    // ---- orbital projections: 8 warps = 8 combos, all pairs ----
    {
        int combo = warp;
        const float* Ws = (combo >= 4) ? Worb_i : Worb_r;
        int s = (combo >> 1) & 1, c = combo & 1;
        #pragma unroll 1
        for (int p = 0; p < PPB; p++) {
            float sum = 0.f;
            int hb = (p*2+s)*RS;
            #pragma unroll
            for (int k = 0; k < 8; k++) {
                int d = lane + 32*k;
                sum = fmaf(rec(Hh, Hl, hb + d), __ldg(Ws + d*2 + c), sum);
            }
            #pragma unroll
            for (int off = 16; off; off >>= 1) sum += __shfl_xor_sync(0xffffffffu, sum, off);
            if (lane == 0) s_orb[p][combo] = sum;
        }
    }
    __syncthreads();

    if (tid < PPB) {
        int p = tid;
        float th0 = s_tp[p][0][0], ph0 = s_tp[p][0][1];
        float th1 = s_tp[p][1][0], ph1 = s_tp[p][1][1];
        float c0, s0, c1, s1;
        sincosf(0.5f*th0, &s0, &c0);
        sincosf(0.5f*th1, &s1, &c1);
        float hd = 0.5f*(ph0 - ph1);
        float chd, shd; sincosf(hd, &shd, &chd);
        float re = (c0*s1 - c1*s0) * chd;
        float im = (c0*s1 + c1*s0) * shd;
        float chord2 = re*re + im*im;
        float trunc = 1.f - expf(-100.f * chord2);
        float t2 = trunc * trunc;
        float a_r = s_orb[p][0], b_r = s_orb[p][1], c_r = s_orb[p][2], d_r = s_orb[p][3];
        float a_i = s_orb[p][4], b_i = s_orb[p][5], c_i = s_orb[p][6], d_i = s_orb[p][7];
        float det_r = (a_r*d_r - a_i*d_i) - (b_r*c_r - b_i*c_i);
        float det_i = (a_r*d_i + a_i*d_r) - (b_r*c_i + b_i*c_r);
        det_r *= t2; det_i *= t2;
        int i = s_ij[p][0], j = s_ij[p][1];
        g_A[i*NE + j] = make_float2(det_r, det_i);
        g_A[j*NE + i] = make_float2(-det_r, -det_i);
    }
}

// ---------------- cusp matrix + bosonic log sum ---------------------------
__global__ void cusp_bos_kernel(const float* __restrict__ electrons)
{
    int i = blockIdx.x, j = threadIdx.x;
    __shared__ double s_red[2][8];
    float thi = electrons[2*i], phi_ = electrons[2*i+1];
    float thj = electrons[2*j], phj  = electrons[2*j+1];
    float ci, si, cj, sj;
    sincosf(0.5f*thi, &si, &ci);
    sincosf(0.5f*thj, &sj, &cj);
    float hd = 0.5f*(phi_ - phj);
    float chd, shd; sincosf(hd, &shd, &chd);
    float er = (ci*sj - si*cj) * chd;
    float ei = (ci*sj + si*cj) * shd;

    float eye = (i == j) ? 1.f : 0.f;
    float cr = er + eye, cim = ei;
    float rc2 = cr*cr + cim*cim;
    float g = expf(-100.f * rc2);
    float2 a = (i == j) ? make_float2(0.f, 0.f) : g_A[i*NE + j];
    a.x += cr * g;
    a.y += cim * g;
    g_A[i*NE + j] = a;

    double lr = 0.0, li = 0.0;
    if (i != j) {
        float rho2 = er*er + ei*ei;
        lr = 0.5 * log((double)(0.01f + rho2));
        li = (double)atan2f(ei, er);
    }
    int lane = j & 31, wrp = j >> 5;
    #pragma unroll
    for (int off = 16; off; off >>= 1) {
        lr += __shfl_xor_sync(0xffffffffu, lr, off);
        li += __shfl_xor_sync(0xffffffffu, li, off);
    }
    if (lane == 0) { s_red[0][wrp] = lr; s_red[1][wrp] = li; }
    __syncthreads();
    if (j == 0) {
        double a0 = 0.0, a1 = 0.0;
        #pragma unroll
        for (int w = 0; w < 8; w++) { a0 += s_red[0][w]; a1 += s_red[1][w]; }
        atomicAdd(&g_acc[0], a0);
        atomicAdd(&g_acc[1], a1);
    }
}

// ---------------- complex LU with partial pivoting (slogdet) --------------
__device__ __forceinline__ float2 cmul(float2 a, float2 b) {
    return make_float2(a.x*b.x - a.y*b.y, a.x*b.y + a.y*b.x);
}

__global__ void __launch_bounds__(1024) lu_kernel()
{
    __shared__ float2 s_prow[256];
    __shared__ float2 s_l[256];
    __shared__ float  s_mx[8];
    __shared__ int    s_mi[8];
    __shared__ float2 s_inv;
    __shared__ int    s_piv;
    int tid = threadIdx.x;
    double logabs = 0.0, argsum = 0.0;
    int par = 0;

    for (int k = 0; k < 256; k++) {
        if (tid < 256) {
            float v = -1.f; int idx = tid;
            if (tid >= k) { float2 a = g_A[tid*256 + k]; v = fabsf(a.x) + fabsf(a.y); }
            #pragma unroll
            for (int off = 16; off; off >>= 1) {
                float ov = __shfl_xor_sync(0xffffffffu, v, off);
                int   oi = __shfl_xor_sync(0xffffffffu, idx, off);
                if (ov > v) { v = ov; idx = oi; }
            }
            if ((tid & 31) == 0) { s_mx[tid>>5] = v; s_mi[tid>>5] = idx; }
        }
        __syncthreads();
        if (tid == 0) {
            float bv = -1.f; int bi = k;
            #pragma unroll
            for (int w = 0; w < 8; w++) if (s_mx[w] > bv) { bv = s_mx[w]; bi = s_mi[w]; }
            s_piv = bi;
        }
        __syncthreads();
        int pv = s_piv;
        if (pv != k && tid < 256) {
            float2 t = g_A[k*256 + tid];
            g_A[k*256 + tid] = g_A[pv*256 + tid];
            g_A[pv*256 + tid] = t;
        }
        __syncthreads();
        if (tid == 0) {
            if (pv != k) par ^= 1;
            float2 u = g_A[k*256 + k];
            double n2 = (double)u.x*u.x + (double)u.y*u.y;
            logabs += 0.5 * log(n2);
            argsum += atan2((double)u.y, (double)u.x);
            float d = u.x*u.x + u.y*u.y;
            s_inv = make_float2(u.x/d, -u.y/d);
        }
        __syncthreads();
        if (tid < 256) {
            s_prow[tid] = g_A[k*256 + tid];
            if (tid > k) {
                float2 l = cmul(g_A[tid*256 + k], s_inv);
                s_l[tid] = l;
                g_A[tid*256 + k] = l;
            }
        }
        __syncthreads();
        {
            int c = tid & 255, r0 = tid >> 8;
            if (c > k) {
                float2 pr = s_prow[c];
                #pragma unroll 4
                for (int i = k + 1 + r0; i < 256; i += 4) {
                    float2 l = s_l[i];
                    float2 a = g_A[i*256 + c];
                    a.x -= l.x*pr.x - l.y*pr.y;
                    a.y -= l.x*pr.y + l.y*pr.x;
                    g_A[i*256 + c] = a;
                }
            }
        }
        __syncthreads();
    }
    if (tid == 0) { g_lu_logabs = logabs; g_lu_arg = argsum; g_lu_par = par; }
}

// ---------------- init + finalize -----------------------------------------
__global__ void init_kernel() { g_acc[0] = 0.0; g_acc[1] = 0.0; }

__global__ void finalize_kernel(float* out)
{
    const double PI = 3.14159265358979323846;
    double logabs = g_lu_logabs;
    double arg = g_lu_arg + (g_lu_par ? PI : 0.0);
    double w = fmod(arg, 2.0*PI);
    if (w >  PI) w -= 2.0*PI;
    if (w <= -PI) w += 2.0*PI;
    out[0] = (float)(0.5*logabs + g_acc[0]);
    out[1] = (float)(0.5*w      + g_acc[1]);
}

// ---------------- launch ---------------------------------------------------
extern "C" void kernel_launch(void* const* d_in, const int* in_sizes, int n_in,
                              void* d_out, int out_size)
{
    const float* electrons = (const float*)d_in[0];
    const float* W_in   = (const float*)d_in[1];
    const float* Wq     = (const float*)d_in[2];
    const float* bq     = (const float*)d_in[3];
    const float* Wk     = (const float*)d_in[4];
    const float* bk     = (const float*)d_in[5];
    const float* Wv     = (const float*)d_in[6];
    const float* bv     = (const float*)d_in[7];
    const float* Wo     = (const float*)d_in[8];
    const float* bo     = (const float*)d_in[9];
    const float* W1     = (const float*)d_in[10];
    const float* ln1_s  = (const float*)d_in[11];
    const float* ln1_b  = (const float*)d_in[12];
    const float* W2     = (const float*)d_in[13];
    const float* b2     = (const float*)d_in[14];
    const float* ln2_s  = (const float*)d_in[15];
    const float* ln2_b  = (const float*)d_in[16];
    const float* Worb_r = (const float*)d_in[17];
    const float* Worb_i = (const float*)d_in[18];

    cudaFuncSetAttribute(pair_kernel, cudaFuncAttributeMaxDynamicSharedMemorySize, SMEM_BYTES);

    wow1_kernel<<<2*257, 256>>>(Wo, W1, bo);
    wvw_kernel<<<257, 256>>>(Wv, bv);
    prep_kernel<<<256, 256>>>(electrons, W_in, Wq, bq, Wk, bk, Wv, bv);
    gram_z_kernel<<<256, 256>>>();
    pbasis_kernel<<<1281, 256>>>(W2, ln1_s, ln1_b);
    convert_host<<<3*256, 256>>>(Wq, Wk, W2);
    init_kernel<<<1, 1>>>();
    pair_kernel<<<NBLOCKS, NTHREADS, SMEM_BYTES>>>(electrons, bq, bk,
                                                   ln1_s, ln1_b, b2, ln2_s, ln2_b,
                                                   Worb_r, Worb_i);
    cusp_bos_kernel<<<NE, NE>>>(electrons);
    lu_kernel<<<1, 1024>>>();
    finalize_kernel<<<1, 1>>>((float*)d_out);
}